// round 8
// baseline (speedup 1.0000x reference)
#include <cuda_runtime.h>
#include <cuda_bf16.h>
#include <math.h>
#include <stdint.h>

#define Bq 2
#define Tq 1024
#define Dq 2048
#define Hq 8
#define DKq 128
#define DVq 256
#define KDq 1024
#define VDq 2048
#define Mrows (Bq*Tq)   // 2048
#define GK 2048         // K for every big GEMM
#define NFUSE 6144      // q(1024) + k(1024) + v(2048) + gate(2048)
#define LCH 64          // scan chunk length
#define NCH (Tq/LCH)    // 16 chunks per sequence
#define NU  (Bq*Hq*NCH) // 256 chunk units

// ------------------------- scratch (device globals) -------------------------
__device__ float g_proj[Mrows*NFUSE];        // fused projection output
__device__ float g_qc[Mrows*KDq];
__device__ float g_kc[Mrows*KDq];
__device__ float g_vc[Mrows*VDq];
__device__ float g_gd[Mrows*Hq];
__device__ float g_bt[Mrows*Hq];
__device__ float g_orow[Mrows*VDq];

// chunked-scan intermediates
__device__ float g_cls[NU*LCH];              // chunk-local cumulative log decay
__device__ float g_uv [NU*LCH*DVq];          // (I+A)^-1 (beta V)
__device__ float g_wm [NU*LCH*DKq];          // (I+A)^-1 diag(beta c) K
__device__ float g_ua [NU*LCH*DVq];          // actual u per step
__device__ float g_s0 [NU*DKq*DVq];          // state at chunk start

// bf16 split (hi/lo) operands
__device__ __nv_bfloat16 g_hh[Mrows*Dq],    g_hl[Mrows*Dq];
__device__ __nv_bfloat16 g_wh[NFUSE*Dq],    g_wl[NFUSE*Dq];
__device__ __nv_bfloat16 g_owh[Dq*VDq],     g_owl[Dq*VDq];
__device__ __nv_bfloat16 g_onh[Mrows*VDq],  g_onl[Mrows*VDq];

// ------------------------- helpers ------------------------------------------
__device__ __forceinline__ uint32_t smem_u32(const void* p) {
    uint32_t a;
    asm("{ .reg .u64 t; cvta.to.shared.u64 t, %1; cvt.u32.u64 %0, t; }" : "=r"(a) : "l"(p));
    return a;
}
__device__ __forceinline__ void cp16(uint32_t dst, const void* src) {
    asm volatile("cp.async.cg.shared.global [%0], [%1], 16;" :: "r"(dst), "l"(src));
}
__device__ __forceinline__ void cp_commit() {
    asm volatile("cp.async.commit_group;" ::: "memory");
}
template <int N>
__device__ __forceinline__ void cp_wait() {
    asm volatile("cp.async.wait_group %0;" :: "n"(N) : "memory");
}
__device__ __forceinline__ void ldsm_x4(uint32_t addr, uint32_t* r) {
    asm volatile("ldmatrix.sync.aligned.m8n8.x4.shared.b16 {%0,%1,%2,%3}, [%4];"
                 : "=r"(r[0]), "=r"(r[1]), "=r"(r[2]), "=r"(r[3]) : "r"(addr));
}
__device__ __forceinline__ void mma_bf16(float* c, const uint32_t* a, const uint32_t* b) {
    asm volatile(
        "mma.sync.aligned.m16n8k16.row.col.f32.bf16.bf16.f32 "
        "{%0,%1,%2,%3}, {%4,%5,%6,%7}, {%8,%9}, {%0,%1,%2,%3};"
        : "+f"(c[0]), "+f"(c[1]), "+f"(c[2]), "+f"(c[3])
        : "r"(a[0]), "r"(a[1]), "r"(a[2]), "r"(a[3]), "r"(b[0]), "r"(b[1]));
}

// ------------------------- split bf16 HMMA GEMM (2-stage, 2 CTA/SM) ---------
#define ROWB 80
#define MATB (128*ROWB)
#define STGB (4*MATB)
#define SMEM_GEMM (2*STGB)

__global__ void __launch_bounds__(256, 2) bgemm_nt_split(
    const __nv_bfloat16* __restrict__ Ah, const __nv_bfloat16* __restrict__ Al,
    const __nv_bfloat16* __restrict__ Bh, const __nv_bfloat16* __restrict__ Bl,
    float* __restrict__ C, int N)
{
    extern __shared__ char smem[];
    const uint32_t sb = smem_u32(smem);
    const int tid = threadIdx.x, wid = tid >> 5, lane = tid & 31;
    const int bm = blockIdx.y * 128, bn = blockIdx.x * 128;
    const int wm = (wid >> 1) * 32;
    const int wn = (wid & 1) * 64;

    float acc[2][8][4];
#pragma unroll
    for (int i = 0; i < 2; i++)
#pragma unroll
        for (int j = 0; j < 8; j++)
#pragma unroll
            for (int l = 0; l < 4; l++) acc[i][j][l] = 0.f;

    const int NC = GK / 32;

#define PREFETCH(cc, ss)                                                          \
    {                                                                             \
        const int kc = (cc) * 32;                                                 \
        const uint32_t stg = sb + (uint32_t)(ss) * STGB;                          \
        _Pragma("unroll")                                                         \
        for (int i = 0; i < 2; i++) {                                             \
            int idx = tid + i * 256;                                              \
            int row = idx >> 2, seg = idx & 3;                                    \
            uint32_t so = (uint32_t)(row * ROWB + seg * 16);                      \
            size_t ea = (size_t)(bm + row) * GK + kc + seg * 8;                   \
            size_t eb = (size_t)(bn + row) * GK + kc + seg * 8;                   \
            cp16(stg + so,            Ah + ea);                                   \
            cp16(stg + MATB + so,     Al + ea);                                   \
            cp16(stg + 2*MATB + so,   Bh + eb);                                   \
            cp16(stg + 3*MATB + so,   Bl + eb);                                   \
        }                                                                         \
        cp_commit();                                                              \
    }

    PREFETCH(0, 0);
    PREFETCH(1, 1);

    const uint32_t a_row = (uint32_t)(wm + (lane & 15));
    const uint32_t a_colb = (uint32_t)((lane >> 4) * 16);
    const uint32_t b_row0 = (uint32_t)(wn + (lane & 7) + ((lane >> 4) << 3));
    const uint32_t b_colb = (uint32_t)(((lane >> 3) & 1) * 16);

    for (int c = 0; c < NC; c++) {
        if (c == NC - 1) cp_wait<0>(); else cp_wait<1>();
        __syncthreads();
        const uint32_t stg = sb + (uint32_t)(c & 1) * STGB;

#pragma unroll
        for (int k16 = 0; k16 < 2; k16++) {
            const uint32_t kb = (uint32_t)(k16 * 32);
            uint32_t a0[2][4], a1[2][4], bb[4][4];

#pragma unroll
            for (int mt = 0; mt < 2; mt++) {
                uint32_t ao = (a_row + mt * 16) * ROWB + kb + a_colb;
                ldsm_x4(stg + ao, a0[mt]);
            }
#pragma unroll
            for (int np = 0; np < 4; np++) {
                uint32_t bo = (b_row0 + np * 16) * ROWB + kb + b_colb;
                ldsm_x4(stg + 2*MATB + bo, bb[np]);
            }
#pragma unroll
            for (int mt = 0; mt < 2; mt++)
#pragma unroll
                for (int np = 0; np < 4; np++) {
                    mma_bf16(acc[mt][np*2],   a0[mt], bb[np]);
                    mma_bf16(acc[mt][np*2+1], a0[mt], bb[np] + 2);
                }

#pragma unroll
            for (int mt = 0; mt < 2; mt++) {
                uint32_t ao = (a_row + mt * 16) * ROWB + kb + a_colb;
                ldsm_x4(stg + MATB + ao, a1[mt]);
            }
#pragma unroll
            for (int mt = 0; mt < 2; mt++)
#pragma unroll
                for (int np = 0; np < 4; np++) {
                    mma_bf16(acc[mt][np*2],   a1[mt], bb[np]);
                    mma_bf16(acc[mt][np*2+1], a1[mt], bb[np] + 2);
                }

#pragma unroll
            for (int np = 0; np < 4; np++) {
                uint32_t bo = (b_row0 + np * 16) * ROWB + kb + b_colb;
                ldsm_x4(stg + 3*MATB + bo, bb[np]);
            }
#pragma unroll
            for (int mt = 0; mt < 2; mt++)
#pragma unroll
                for (int np = 0; np < 4; np++) {
                    mma_bf16(acc[mt][np*2],   a0[mt], bb[np]);
                    mma_bf16(acc[mt][np*2+1], a0[mt], bb[np] + 2);
                }
        }
        __syncthreads();
        if (c + 2 < NC) PREFETCH(c + 2, c & 1);
    }
#undef PREFETCH

#pragma unroll
    for (int mt = 0; mt < 2; mt++) {
        int r0 = bm + wm + mt * 16 + (lane >> 2);
#pragma unroll
        for (int nt = 0; nt < 8; nt++) {
            int col = bn + wn + nt * 8 + (lane & 3) * 2;
            float2 v0 = make_float2(acc[mt][nt][0], acc[mt][nt][1]);
            float2 v1 = make_float2(acc[mt][nt][2], acc[mt][nt][3]);
            *(float2*)(C + (size_t)r0 * N + col)       = v0;
            *(float2*)(C + (size_t)(r0 + 8) * N + col) = v1;
        }
    }
}

// ------------------------- fp32 -> bf16 hi/lo split -------------------------
__device__ __forceinline__ void split4(float4 v, __nv_bfloat16* hi, __nv_bfloat16* lo) {
    __nv_bfloat16 hx = __float2bfloat16(v.x), hy = __float2bfloat16(v.y);
    __nv_bfloat16 hz = __float2bfloat16(v.z), hw = __float2bfloat16(v.w);
    __nv_bfloat162 h0, h1, l0, l1;
    h0.x = hx; h0.y = hy; h1.x = hz; h1.y = hw;
    l0.x = __float2bfloat16(v.x - __bfloat162float(hx));
    l0.y = __float2bfloat16(v.y - __bfloat162float(hy));
    l1.x = __float2bfloat16(v.z - __bfloat162float(hz));
    l1.y = __float2bfloat16(v.w - __bfloat162float(hw));
    *(__nv_bfloat162*)(hi)     = h0;
    *(__nv_bfloat162*)(hi + 2) = h1;
    *(__nv_bfloat162*)(lo)     = l0;
    *(__nv_bfloat162*)(lo + 2) = l1;
}

__global__ void cvt_split(const float* __restrict__ x,
                          __nv_bfloat16* __restrict__ hi,
                          __nv_bfloat16* __restrict__ lo, int n)
{
    int i = (blockIdx.x * blockDim.x + threadIdx.x) * 4;
    if (i >= n) return;
    split4(*(const float4*)(x + i), hi + i, lo + i);
}

__global__ void cvt_split_w4(const float* __restrict__ qw, const float* __restrict__ kw,
                             const float* __restrict__ vw, const float* __restrict__ gw,
                             __nv_bfloat16* __restrict__ hi, __nv_bfloat16* __restrict__ lo)
{
    int i = (blockIdx.x * blockDim.x + threadIdx.x) * 4;
    int row = i >> 11;
    int col = i & 2047;
    const float* src;
    if (row < 1024)      src = qw + (size_t)row * Dq + col;
    else if (row < 2048) src = kw + (size_t)(row - 1024) * Dq + col;
    else if (row < 4096) src = vw + (size_t)(row - 2048) * Dq + col;
    else                 src = gw + (size_t)(row - 4096) * Dq + col;
    split4(*(const float4*)src, hi + i, lo + i);
}

// ------------------------- a/b projections -> decay g and beta --------------
__device__ __forceinline__ float softplus_f(float x) {
    return fmaxf(x, 0.f) + log1pf(expf(-fabsf(x)));
}

__global__ void proj_ab_kernel(const float* __restrict__ h,
                               const float* __restrict__ a_w,
                               const float* __restrict__ b_w,
                               const float* __restrict__ A_log,
                               const float* __restrict__ dt_bias,
                               float* __restrict__ gd, float* __restrict__ bt)
{
    int w = (blockIdx.x * blockDim.x + threadIdx.x) >> 5;
    int lane = threadIdx.x & 31;
    if (w >= Mrows) return;
    const float* hr = h + (size_t)w * Dq;
    float acc[16];
#pragma unroll
    for (int p = 0; p < 16; p++) acc[p] = 0.f;
    for (int j = lane * 4; j < Dq; j += 128) {
        float4 hv = *(const float4*)(hr + j);
#pragma unroll
        for (int p = 0; p < 8; p++) {
            float4 av = *(const float4*)(a_w + (size_t)p * Dq + j);
            acc[p] += hv.x * av.x + hv.y * av.y + hv.z * av.z + hv.w * av.w;
            float4 bv = *(const float4*)(b_w + (size_t)p * Dq + j);
            acc[8 + p] += hv.x * bv.x + hv.y * bv.y + hv.z * bv.z + hv.w * bv.w;
        }
    }
#pragma unroll
    for (int p = 0; p < 16; p++)
#pragma unroll
        for (int m = 16; m; m >>= 1)
            acc[p] += __shfl_xor_sync(0xffffffffu, acc[p], m);

    if (lane < 8) {
        float x = acc[lane] + dt_bias[lane];
        gd[w * Hq + lane] = -expf(A_log[lane]) * softplus_f(x);
    } else if (lane < 16) {
        int p = lane - 8;
        bt[w * Hq + p] = 1.f / (1.f + expf(-acc[lane]));
    }
}

// ---------------- fused conv+SiLU+l2norm for q/k (head dim 128) -------------
__global__ void conv_l2_kernel(const float* __restrict__ P, int colofs,
                               const float* __restrict__ w, float* __restrict__ out)
{
    int gwp = (blockIdx.x * blockDim.x + threadIdx.x) >> 5;
    int lane = threadIdx.x & 31;
    int row = gwp >> 3, hh = gwp & 7;
    int t = row & (Tq - 1);
    int c = hh * 128 + lane * 4;
    const float* base = P + (size_t)row * NFUSE + colofs + c;
    float4 x0 = *(const float4*)base;
    float4 x1 = make_float4(0,0,0,0), x2 = x1, x3 = x1;
    if (t >= 1) x1 = *(const float4*)(base - NFUSE);
    if (t >= 2) x2 = *(const float4*)(base - 2*NFUSE);
    if (t >= 3) x3 = *(const float4*)(base - 3*NFUSE);
    float4 wc0 = *(const float4*)(w + (size_t)(c + 0) * 4);
    float4 wc1 = *(const float4*)(w + (size_t)(c + 1) * 4);
    float4 wc2 = *(const float4*)(w + (size_t)(c + 2) * 4);
    float4 wc3 = *(const float4*)(w + (size_t)(c + 3) * 4);
    float v0 = x0.x*wc0.w + x1.x*wc0.z + x2.x*wc0.y + x3.x*wc0.x;
    float v1 = x0.y*wc1.w + x1.y*wc1.z + x2.y*wc1.y + x3.y*wc1.x;
    float v2 = x0.z*wc2.w + x1.z*wc2.z + x2.z*wc2.y + x3.z*wc2.x;
    float v3 = x0.w*wc3.w + x1.w*wc3.z + x2.w*wc3.y + x3.w*wc3.x;
    v0 = v0 / (1.f + expf(-v0));
    v1 = v1 / (1.f + expf(-v1));
    v2 = v2 / (1.f + expf(-v2));
    v3 = v3 / (1.f + expf(-v3));
    float ss = v0*v0 + v1*v1 + v2*v2 + v3*v3;
#pragma unroll
    for (int m = 16; m; m >>= 1) ss += __shfl_xor_sync(0xffffffffu, ss, m);
    float r = rsqrtf(ss + 1e-6f);
    *(float4*)(out + (size_t)row * KDq + c) =
        make_float4(v0 * r, v1 * r, v2 * r, v3 * r);
}

// ---------------- conv+SiLU for v (elementwise, strided read) ---------------
__global__ void conv_silu_stride(const float* __restrict__ P, int colofs,
                                 const float* __restrict__ w, float* __restrict__ out)
{
    int i = blockIdx.x * blockDim.x + threadIdx.x;
    int c = i % VDq;
    int row = i / VDq;
    int t = row & (Tq - 1);
    const float* base = P + (size_t)row * NFUSE + colofs + c;
    float4 wc = *(const float4*)(w + (size_t)c * 4);
    float acc = base[0] * wc.w;
    if (t >= 1) acc += base[-1 * NFUSE] * wc.z;
    if (t >= 2) acc += base[-2 * NFUSE] * wc.y;
    if (t >= 3) acc += base[-3 * NFUSE] * wc.x;
    out[i] = acc / (1.f + expf(-acc));
}

// ======================= chunked gated delta-rule scan ======================
// K1: per chunk-unit, build A and solve (I+A)[u_v | W] = [beta V | beta c K]
#define K1_SMEM ((64*128 + 64*256 + 64*64 + 64*3 + 16)*4)

__global__ void __launch_bounds__(384) chunk_solve_kernel(
    const float* __restrict__ kc, const float* __restrict__ vc,
    const float* __restrict__ gd, const float* __restrict__ bt,
    float* __restrict__ uv, float* __restrict__ wm, float* __restrict__ clsg)
{
    extern __shared__ float sm[];
    float* ks  = sm;               // [64][128]
    float* vs  = ks + 64*128;      // [64][256]
    float* As  = vs + 64*256;      // [64][64]
    float* cls = As + 64*64;       // [64]
    float* bes = cls + 64;         // [64]
    float* ec  = bes + 64;         // [64] = expf(cls)
    const int cu = blockIdx.x;
    const int ch = cu % NCH, bh = cu / NCH;
    const int h = bh % Hq, b = bh / Hq;
    const int row0 = b * Tq + ch * LCH;
    const int tid = threadIdx.x;

    for (int i = tid; i < 64*32; i += 384) {
        int t = i >> 5, f = i & 31;
        *(float4*)(ks + t*128 + f*4) =
            *(const float4*)(kc + (size_t)(row0+t)*KDq + h*DKq + f*4);
    }
    for (int i = tid; i < 64*64; i += 384) {
        int t = i >> 6, f = i & 63;
        *(float4*)(vs + t*256 + f*4) =
            *(const float4*)(vc + (size_t)(row0+t)*VDq + h*DVq + f*4);
    }
    if (tid < 64) bes[tid] = bt[(row0+tid)*Hq + h];
    if (tid == 0) {
        float a = 0.f;
        for (int t = 0; t < 64; t++) { a += gd[(row0+t)*Hq + h]; cls[t] = a; }
    }
    __syncthreads();
    if (tid < 64) { ec[tid] = expf(cls[tid]); clsg[cu*64 + tid] = cls[tid]; }
    __syncthreads();

    // A[t][i] = beta_t * exp(cls_t - cls_i) * (k_t . k_i), i < t; 0 elsewhere
    for (int p = tid; p < 64*64; p += 384) {
        int t = p >> 6, i = p & 63;
        float a = 0.f;
        if (i < t) {
            const float* kt = ks + t*128;
            const float* ki = ks + i*128;
            float d0=0.f,d1=0.f,d2=0.f,d3=0.f;
            for (int r = 0; r < 128; r += 4) {
                d0 += kt[r+0]*ki[r+0]; d1 += kt[r+1]*ki[r+1];
                d2 += kt[r+2]*ki[r+2]; d3 += kt[r+3]*ki[r+3];
            }
            a = bes[t] * expf(cls[t]-cls[i]) * ((d0+d1)+(d2+d3));
        }
        As[p] = a;
    }
    __syncthreads();

    // forward substitution, one column per thread (384 = 256 v + 128 k cols)
    const int col = tid;
    float x[64];
#pragma unroll
    for (int t = 0; t < 64; t++) {
        float acc;
        if (col < 256) acc = bes[t] * vs[t*256 + col];
        else           acc = bes[t] * ec[t] * ks[t*128 + (col - 256)];
#pragma unroll
        for (int i = 0; i < t; i++) acc -= As[t*64 + i] * x[i];
        x[t] = acc;
    }
    if (col < 256) {
        for (int t = 0; t < 64; t++)
            uv[((size_t)cu*64 + t)*256 + col] = x[t];
    } else {
        int r = col - 256;
        for (int t = 0; t < 64; t++)
            wm[((size_t)cu*64 + t)*128 + r] = x[t];
    }
}

// K2: sequential over chunks: u = uv - W S0 ; S = eL S0 + (e k)^T u
#define K2_SMEM ((128*32 + 64*128 + 64*128 + 64*32 + 64 + 16)*4)

__global__ void __launch_bounds__(128) chunk_state_kernel(
    const float* __restrict__ kc, const float* __restrict__ wm,
    const float* __restrict__ uv, const float* __restrict__ clsg,
    float* __restrict__ ua, float* __restrict__ s0)
{
    extern __shared__ float sm[];
    float* Ssm = sm;               // [128][32]
    float* Wsm = Ssm + 128*32;     // [64][128]
    float* ksm = Wsm + 64*128;     // [64][128]
    float* Usm = ksm + 64*128;     // [64][32]
    float* ets = Usm + 64*32;      // [64]
    const int cg = blockIdx.x, bh = blockIdx.y;
    const int h = bh & 7, b = bh >> 3;
    const int c0 = cg * 32;
    const int tid = threadIdx.x;

    for (int i = tid; i < 1024; i += 128) {
        *(float4*)(Ssm + i*4) = make_float4(0.f, 0.f, 0.f, 0.f);
    }
    __syncthreads();

    for (int ch = 0; ch < NCH; ch++) {
        const int cu = bh * NCH + ch;
        const int row0 = b * Tq + ch * LCH;
        const float clsL = clsg[cu*64 + 63];
        const float eL = expf(clsL);
        for (int i = tid; i < 2048; i += 128) {
            *(float4*)(Wsm + i*4) = *(const float4*)(wm + (size_t)cu*64*128 + i*4);
            int t = i >> 5, f = i & 31;
            *(float4*)(ksm + t*128 + f*4) =
                *(const float4*)(kc + (size_t)(row0+t)*KDq + h*DKq + f*4);
        }
        if (tid < 64) ets[tid] = expf(clsL - clsg[cu*64 + tid]);
        // store S0 (state before this chunk)
        for (int i = tid; i < 1024; i += 128) {
            int r = i >> 3, c4 = i & 7;
            *(float4*)(s0 + ((size_t)cu*128 + r)*256 + c0 + c4*4) =
                *(float4*)(Ssm + r*32 + c4*4);
        }
        __syncthreads();

        // U = uv - W*S ; Usm holds e_t * u
        {
            int cq = tid & 7, tq = tid >> 3;
            for (int it = 0; it < 4; it++) {
                int t = tq + it*16;
                float4 acc = *(const float4*)(uv + ((size_t)cu*64 + t)*256 + c0 + cq*4);
                const float* wr = Wsm + t*128;
#pragma unroll 8
                for (int r = 0; r < 128; r++) {
                    float w = wr[r];
                    float4 s = *(float4*)(Ssm + r*32 + cq*4);
                    acc.x -= w*s.x; acc.y -= w*s.y; acc.z -= w*s.z; acc.w -= w*s.w;
                }
                *(float4*)(ua + ((size_t)cu*64 + t)*256 + c0 + cq*4) = acc;
                float e = ets[t];
                acc.x *= e; acc.y *= e; acc.z *= e; acc.w *= e;
                *(float4*)(Usm + t*32 + cq*4) = acc;
            }
        }
        __syncthreads();

        // S = eL*S + k^T (e u)
        {
            int cq = tid & 7, rq = tid >> 3;
            for (int j = 0; j < 8; j++) {
                int r = rq*8 + j;
                float4 s = *(float4*)(Ssm + r*32 + cq*4);
                s.x *= eL; s.y *= eL; s.z *= eL; s.w *= eL;
#pragma unroll 8
                for (int t = 0; t < 64; t++) {
                    float kk = ksm[t*128 + r];
                    float4 u = *(float4*)(Usm + t*32 + cq*4);
                    s.x += kk*u.x; s.y += kk*u.y; s.z += kk*u.z; s.w += kk*u.w;
                }
                *(float4*)(Ssm + r*32 + cq*4) = s;
            }
        }
        __syncthreads();
    }
}

// K3: outputs o_t = e^{cls_t} q_t^T S0 + sum_{i<=t} Gq[t,i] u_i
#define K3_SMEM ((64*128 + 64*128 + 64*64 + 64*256 + 64 + 16)*4)

__global__ void __launch_bounds__(256) chunk_out_kernel(
    const float* __restrict__ qc, const float* __restrict__ kc,
    const float* __restrict__ ua, const float* __restrict__ s0,
    const float* __restrict__ clsg, float* __restrict__ o)
{
    extern __shared__ float sm[];
    float* qs  = sm;                // [64][128]
    float* ks  = qs + 64*128;       // [64][128]
    float* Gq  = ks + 64*128;       // [64][64]
    float* uas = Gq + 64*64;        // [64][256]
    float* cls = uas + 64*256;      // [64]
    const int cu = blockIdx.x;
    const int ch = cu % NCH, bh = cu / NCH;
    const int h = bh & 7, b = bh >> 3;
    const int row0 = b * Tq + ch * LCH;
    const int tid = threadIdx.x;

    for (int i = tid; i < 2048; i += 256) {
        int t = i >> 5, f = i & 31;
        size_t go = (size_t)(row0+t)*KDq + h*DKq + f*4;
        *(float4*)(qs + t*128 + f*4) = *(const float4*)(qc + go);
        *(float4*)(ks + t*128 + f*4) = *(const float4*)(kc + go);
    }
    for (int i = tid; i < 4096; i += 256)
        *(float4*)(uas + i*4) = *(const float4*)(ua + (size_t)cu*64*256 + i*4);
    if (tid < 64) cls[tid] = clsg[cu*64 + tid];
    __syncthreads();

    for (int p = tid; p < 64*64; p += 256) {
        int t = p >> 6, i = p & 63;
        float g = 0.f;
        if (i <= t) {
            const float* qt = qs + t*128;
            const float* ki = ks + i*128;
            float d0=0.f,d1=0.f,d2=0.f,d3=0.f;
            for (int r = 0; r < 128; r += 4) {
                d0 += qt[r+0]*ki[r+0]; d1 += qt[r+1]*ki[r+1];
                d2 += qt[r+2]*ki[r+2]; d3 += qt[r+3]*ki[r+3];
            }
            g = expf(cls[t]-cls[i]) * ((d0+d1)+(d2+d3));
        }
        Gq[p] = g;
    }
    __syncthreads();

    const int col = tid;
    float acc[64];
#pragma unroll
    for (int t = 0; t < 64; t++) acc[t] = 0.f;
    const float* s0p = s0 + (size_t)cu*128*256 + col;
    for (int r = 0; r < 128; r++) {
        float s = s0p[(size_t)r * 256];
#pragma unroll
        for (int t = 0; t < 64; t++) acc[t] += qs[t*128 + r] * s;
    }
#pragma unroll
    for (int t = 0; t < 64; t++) acc[t] *= expf(cls[t]);
    for (int i2 = 0; i2 < 64; i2++) {
        float u = uas[i2*256 + col];
#pragma unroll
        for (int t = 0; t < 64; t++) acc[t] += Gq[t*64 + i2] * u;
    }
    const float scale = 0.08838834764831843f;
    for (int t = 0; t < 64; t++)
        o[(size_t)(row0+t)*VDq + h*DVq + col] = scale * acc[t];
}

// ------------------------- gated RMSNorm -> bf16 hi/lo ----------------------
__global__ void rmsnorm_gate_kernel(const float* __restrict__ o,
                                    const float* __restrict__ P,
                                    const float* __restrict__ nw,
                                    __nv_bfloat16* __restrict__ oh,
                                    __nv_bfloat16* __restrict__ ol)
{
    int w = (blockIdx.x * blockDim.x + threadIdx.x) >> 5;
    int lane = threadIdx.x & 31;
    int row = w >> 3, hh = w & 7;
    const float* orow = o + (size_t)w * DVq;
    float4 o0 = *(const float4*)(orow + lane * 4);
    float4 o1 = *(const float4*)(orow + 128 + lane * 4);
    float ss = o0.x * o0.x + o0.y * o0.y + o0.z * o0.z + o0.w * o0.w
             + o1.x * o1.x + o1.y * o1.y + o1.z * o1.z + o1.w * o1.w;
#pragma unroll
    for (int m = 16; m; m >>= 1) ss += __shfl_xor_sync(0xffffffffu, ss, m);
    float r = rsqrtf(ss * (1.f / 256.f) + 1e-5f);
    const float* grow = P + (size_t)row * NFUSE + 4096 + hh * DVq;
    float4 g0 = *(const float4*)(grow + lane * 4);
    float4 g1 = *(const float4*)(grow + 128 + lane * 4);
    float4 w0 = *(const float4*)(nw + lane * 4);
    float4 w1 = *(const float4*)(nw + 128 + lane * 4);
    float f[8];
    f[0] = o0.x * r * w0.x * (g0.x / (1.f + expf(-g0.x)));
    f[1] = o0.y * r * w0.y * (g0.y / (1.f + expf(-g0.y)));
    f[2] = o0.z * r * w0.z * (g0.z / (1.f + expf(-g0.z)));
    f[3] = o0.w * r * w0.w * (g0.w / (1.f + expf(-g0.w)));
    f[4] = o1.x * r * w1.x * (g1.x / (1.f + expf(-g1.x)));
    f[5] = o1.y * r * w1.y * (g1.y / (1.f + expf(-g1.y)));
    f[6] = o1.z * r * w1.z * (g1.z / (1.f + expf(-g1.z)));
    f[7] = o1.w * r * w1.w * (g1.w / (1.f + expf(-g1.w)));
#pragma unroll
    for (int half = 0; half < 2; half++) {
        size_t base = (size_t)w * DVq + half * 128 + lane * 4;
        float a = f[half*4+0], b2 = f[half*4+1], c = f[half*4+2], d = f[half*4+3];
        split4(make_float4(a, b2, c, d), oh + base, ol + base);
    }
}

// ------------------------- launch -------------------------------------------
extern "C" void kernel_launch(void* const* d_in, const int* in_sizes, int n_in,
                              void* d_out, int out_size)
{
    const float* h        = (const float*)d_in[0];
    const float* q_w      = (const float*)d_in[1];
    const float* k_w      = (const float*)d_in[2];
    const float* v_w      = (const float*)d_in[3];
    const float* a_w      = (const float*)d_in[4];
    const float* b_w      = (const float*)d_in[5];
    const float* g_w      = (const float*)d_in[6];
    const float* o_w      = (const float*)d_in[7];
    const float* q_conv_w = (const float*)d_in[8];
    const float* k_conv_w = (const float*)d_in[9];
    const float* v_conv_w = (const float*)d_in[10];
    const float* A_log    = (const float*)d_in[11];
    const float* dt_bias  = (const float*)d_in[12];
    const float* o_norm_w = (const float*)d_in[13];
    float* out = (float*)d_out;

    float *P, *qc, *kc, *vc, *gd, *bt, *orow;
    float *cls, *uv, *wmp, *uap, *s0p;
    cudaGetSymbolAddress((void**)&P, g_proj);
    cudaGetSymbolAddress((void**)&qc, g_qc);
    cudaGetSymbolAddress((void**)&kc, g_kc);
    cudaGetSymbolAddress((void**)&vc, g_vc);
    cudaGetSymbolAddress((void**)&gd, g_gd);
    cudaGetSymbolAddress((void**)&bt, g_bt);
    cudaGetSymbolAddress((void**)&orow, g_orow);
    cudaGetSymbolAddress((void**)&cls, g_cls);
    cudaGetSymbolAddress((void**)&uv, g_uv);
    cudaGetSymbolAddress((void**)&wmp, g_wm);
    cudaGetSymbolAddress((void**)&uap, g_ua);
    cudaGetSymbolAddress((void**)&s0p, g_s0);

    __nv_bfloat16 *hh, *hl, *wh, *wl, *owh, *owl, *onh, *onl;
    cudaGetSymbolAddress((void**)&hh, g_hh);   cudaGetSymbolAddress((void**)&hl, g_hl);
    cudaGetSymbolAddress((void**)&wh, g_wh);   cudaGetSymbolAddress((void**)&wl, g_wl);
    cudaGetSymbolAddress((void**)&owh, g_owh); cudaGetSymbolAddress((void**)&owl, g_owl);
    cudaGetSymbolAddress((void**)&onh, g_onh); cudaGetSymbolAddress((void**)&onl, g_onl);

    cudaFuncSetAttribute(bgemm_nt_split, cudaFuncAttributeMaxDynamicSharedMemorySize, SMEM_GEMM);
    cudaFuncSetAttribute(chunk_solve_kernel, cudaFuncAttributeMaxDynamicSharedMemorySize, K1_SMEM);
    cudaFuncSetAttribute(chunk_state_kernel, cudaFuncAttributeMaxDynamicSharedMemorySize, K2_SMEM);
    cudaFuncSetAttribute(chunk_out_kernel,   cudaFuncAttributeMaxDynamicSharedMemorySize, K3_SMEM);

    // 0) bf16 hi/lo splits
    cvt_split<<<(Mrows*Dq/4 + 255)/256, 256>>>(h, hh, hl, Mrows*Dq);
    cvt_split_w4<<<(NFUSE*Dq/4 + 255)/256, 256>>>(q_w, k_w, v_w, g_w, wh, wl);
    cvt_split<<<(Dq*VDq/4 + 255)/256, 256>>>(o_w, owh, owl, Dq*VDq);

    // 1) fused q|k|v|gate projection on tensor cores
    bgemm_nt_split<<<dim3(NFUSE/128, Mrows/128), 256, SMEM_GEMM>>>(hh, hl, wh, wl, P, NFUSE);

    // 2) a/b projections -> decay + beta
    proj_ab_kernel<<<(Mrows * 32) / 256, 256>>>(h, a_w, b_w, A_log, dt_bias, gd, bt);

    // 3) conv+SiLU+l2norm for q,k ; conv+SiLU for v
    conv_l2_kernel<<<(Mrows * Hq * 32) / 256, 256>>>(P, 0,    q_conv_w, qc);
    conv_l2_kernel<<<(Mrows * Hq * 32) / 256, 256>>>(P, 1024, k_conv_w, kc);
    conv_silu_stride<<<(Mrows * VDq) / 256, 256>>>(P, 2048, v_conv_w, vc);

    // 4) chunked gated delta-rule scan
    chunk_solve_kernel<<<NU, 384, K1_SMEM>>>(kc, vc, gd, bt, uv, wmp, cls);
    chunk_state_kernel<<<dim3(8, Bq*Hq), 128, K2_SMEM>>>(kc, wmp, uv, cls, uap, s0p);
    chunk_out_kernel<<<NU, 256, K3_SMEM>>>(qc, kc, uap, s0p, cls, orow);

    // 5) gated RMSNorm (+ bf16 hi/lo split)
    rmsnorm_gate_kernel<<<(Mrows * Hq * 32) / 256, 256>>>(orow, P, o_norm_w, onh, onl);

    // 6) output projection -> d_out
    bgemm_nt_split<<<dim3(Dq/128, Mrows/128), 256, SMEM_GEMM>>>(onh, onl, owh, owl, out, Dq);
}

// round 9
// speedup vs baseline: 1.2060x; 1.2060x over previous
#include <cuda_runtime.h>
#include <cuda_bf16.h>
#include <math.h>
#include <stdint.h>

#define Bq 2
#define Tq 1024
#define Dq 2048
#define Hq 8
#define DKq 128
#define DVq 256
#define KDq 1024
#define VDq 2048
#define Mrows (Bq*Tq)   // 2048
#define GK 2048         // K for every big GEMM
#define NFUSE 6144      // q(1024) + k(1024) + v(2048) + gate(2048)
#define LCH 64          // scan chunk length
#define NCH (Tq/LCH)    // 16 chunks per sequence
#define NU  (Bq*Hq*NCH) // 256 chunk units

// ------------------------- scratch (device globals) -------------------------
__device__ float g_proj[Mrows*NFUSE];
__device__ float g_qc[Mrows*KDq];
__device__ float g_kc[Mrows*KDq];
__device__ float g_vc[Mrows*VDq];
__device__ float g_gd[Mrows*Hq];
__device__ float g_bt[Mrows*Hq];
__device__ float g_orow[Mrows*VDq];

// chunked-scan intermediates
__device__ float g_cls[NU*LCH];
__device__ float g_uv [NU*LCH*DVq];
__device__ float g_wm [NU*LCH*DKq];
__device__ float g_ua [NU*LCH*DVq];
__device__ float g_s0 [NU*DKq*DVq];

// bf16 split (hi/lo) operands
__device__ __nv_bfloat16 g_hh[Mrows*Dq],    g_hl[Mrows*Dq];
__device__ __nv_bfloat16 g_wh[NFUSE*Dq],    g_wl[NFUSE*Dq];
__device__ __nv_bfloat16 g_owh[Dq*VDq],     g_owl[Dq*VDq];
__device__ __nv_bfloat16 g_onh[Mrows*VDq],  g_onl[Mrows*VDq];

// ------------------------- helpers ------------------------------------------
__device__ __forceinline__ uint32_t smem_u32(const void* p) {
    uint32_t a;
    asm("{ .reg .u64 t; cvta.to.shared.u64 t, %1; cvt.u32.u64 %0, t; }" : "=r"(a) : "l"(p));
    return a;
}
__device__ __forceinline__ void cp16(uint32_t dst, const void* src) {
    asm volatile("cp.async.cg.shared.global [%0], [%1], 16;" :: "r"(dst), "l"(src));
}
__device__ __forceinline__ void cp_commit() {
    asm volatile("cp.async.commit_group;" ::: "memory");
}
template <int N>
__device__ __forceinline__ void cp_wait() {
    asm volatile("cp.async.wait_group %0;" :: "n"(N) : "memory");
}
__device__ __forceinline__ void ldsm_x4(uint32_t addr, uint32_t* r) {
    asm volatile("ldmatrix.sync.aligned.m8n8.x4.shared.b16 {%0,%1,%2,%3}, [%4];"
                 : "=r"(r[0]), "=r"(r[1]), "=r"(r[2]), "=r"(r[3]) : "r"(addr));
}
__device__ __forceinline__ void mma_bf16(float* c, const uint32_t* a, const uint32_t* b) {
    asm volatile(
        "mma.sync.aligned.m16n8k16.row.col.f32.bf16.bf16.f32 "
        "{%0,%1,%2,%3}, {%4,%5,%6,%7}, {%8,%9}, {%0,%1,%2,%3};"
        : "+f"(c[0]), "+f"(c[1]), "+f"(c[2]), "+f"(c[3])
        : "r"(a[0]), "r"(a[1]), "r"(a[2]), "r"(a[3]), "r"(b[0]), "r"(b[1]));
}

// ------------------------- split bf16 HMMA GEMM (2-stage, 2 CTA/SM) ---------
#define ROWB 80
#define MATB (128*ROWB)
#define STGB (4*MATB)
#define SMEM_GEMM (2*STGB)

__global__ void __launch_bounds__(256, 2) bgemm_nt_split(
    const __nv_bfloat16* __restrict__ Ah, const __nv_bfloat16* __restrict__ Al,
    const __nv_bfloat16* __restrict__ Bh, const __nv_bfloat16* __restrict__ Bl,
    float* __restrict__ C, int N)
{
    extern __shared__ char smem[];
    const uint32_t sb = smem_u32(smem);
    const int tid = threadIdx.x, wid = tid >> 5, lane = tid & 31;
    const int bm = blockIdx.y * 128, bn = blockIdx.x * 128;
    const int wm = (wid >> 1) * 32;
    const int wn = (wid & 1) * 64;

    float acc[2][8][4];
#pragma unroll
    for (int i = 0; i < 2; i++)
#pragma unroll
        for (int j = 0; j < 8; j++)
#pragma unroll
            for (int l = 0; l < 4; l++) acc[i][j][l] = 0.f;

    const int NC = GK / 32;

#define PREFETCH(cc, ss)                                                          \
    {                                                                             \
        const int kc = (cc) * 32;                                                 \
        const uint32_t stg = sb + (uint32_t)(ss) * STGB;                          \
        _Pragma("unroll")                                                         \
        for (int i = 0; i < 2; i++) {                                             \
            int idx = tid + i * 256;                                              \
            int row = idx >> 2, seg = idx & 3;                                    \
            uint32_t so = (uint32_t)(row * ROWB + seg * 16);                      \
            size_t ea = (size_t)(bm + row) * GK + kc + seg * 8;                   \
            size_t eb = (size_t)(bn + row) * GK + kc + seg * 8;                   \
            cp16(stg + so,            Ah + ea);                                   \
            cp16(stg + MATB + so,     Al + ea);                                   \
            cp16(stg + 2*MATB + so,   Bh + eb);                                   \
            cp16(stg + 3*MATB + so,   Bl + eb);                                   \
        }                                                                         \
        cp_commit();                                                              \
    }

    PREFETCH(0, 0);
    PREFETCH(1, 1);

    const uint32_t a_row = (uint32_t)(wm + (lane & 15));
    const uint32_t a_colb = (uint32_t)((lane >> 4) * 16);
    const uint32_t b_row0 = (uint32_t)(wn + (lane & 7) + ((lane >> 4) << 3));
    const uint32_t b_colb = (uint32_t)(((lane >> 3) & 1) * 16);

    for (int c = 0; c < NC; c++) {
        if (c == NC - 1) cp_wait<0>(); else cp_wait<1>();
        __syncthreads();
        const uint32_t stg = sb + (uint32_t)(c & 1) * STGB;

#pragma unroll
        for (int k16 = 0; k16 < 2; k16++) {
            const uint32_t kb = (uint32_t)(k16 * 32);
            uint32_t a0[2][4], a1[2][4], bb[4][4];

#pragma unroll
            for (int mt = 0; mt < 2; mt++) {
                uint32_t ao = (a_row + mt * 16) * ROWB + kb + a_colb;
                ldsm_x4(stg + ao, a0[mt]);
            }
#pragma unroll
            for (int np = 0; np < 4; np++) {
                uint32_t bo = (b_row0 + np * 16) * ROWB + kb + b_colb;
                ldsm_x4(stg + 2*MATB + bo, bb[np]);
            }
#pragma unroll
            for (int mt = 0; mt < 2; mt++)
#pragma unroll
                for (int np = 0; np < 4; np++) {
                    mma_bf16(acc[mt][np*2],   a0[mt], bb[np]);
                    mma_bf16(acc[mt][np*2+1], a0[mt], bb[np] + 2);
                }

#pragma unroll
            for (int mt = 0; mt < 2; mt++) {
                uint32_t ao = (a_row + mt * 16) * ROWB + kb + a_colb;
                ldsm_x4(stg + MATB + ao, a1[mt]);
            }
#pragma unroll
            for (int mt = 0; mt < 2; mt++)
#pragma unroll
                for (int np = 0; np < 4; np++) {
                    mma_bf16(acc[mt][np*2],   a1[mt], bb[np]);
                    mma_bf16(acc[mt][np*2+1], a1[mt], bb[np] + 2);
                }

#pragma unroll
            for (int np = 0; np < 4; np++) {
                uint32_t bo = (b_row0 + np * 16) * ROWB + kb + b_colb;
                ldsm_x4(stg + 3*MATB + bo, bb[np]);
            }
#pragma unroll
            for (int mt = 0; mt < 2; mt++)
#pragma unroll
                for (int np = 0; np < 4; np++) {
                    mma_bf16(acc[mt][np*2],   a0[mt], bb[np]);
                    mma_bf16(acc[mt][np*2+1], a0[mt], bb[np] + 2);
                }
        }
        __syncthreads();
        if (c + 2 < NC) PREFETCH(c + 2, c & 1);
    }
#undef PREFETCH

#pragma unroll
    for (int mt = 0; mt < 2; mt++) {
        int r0 = bm + wm + mt * 16 + (lane >> 2);
#pragma unroll
        for (int nt = 0; nt < 8; nt++) {
            int col = bn + wn + nt * 8 + (lane & 3) * 2;
            float2 v0 = make_float2(acc[mt][nt][0], acc[mt][nt][1]);
            float2 v1 = make_float2(acc[mt][nt][2], acc[mt][nt][3]);
            *(float2*)(C + (size_t)r0 * N + col)       = v0;
            *(float2*)(C + (size_t)(r0 + 8) * N + col) = v1;
        }
    }
}

// ------------------------- fp32 -> bf16 hi/lo split -------------------------
__device__ __forceinline__ void split4(float4 v, __nv_bfloat16* hi, __nv_bfloat16* lo) {
    __nv_bfloat16 hx = __float2bfloat16(v.x), hy = __float2bfloat16(v.y);
    __nv_bfloat16 hz = __float2bfloat16(v.z), hw = __float2bfloat16(v.w);
    __nv_bfloat162 h0, h1, l0, l1;
    h0.x = hx; h0.y = hy; h1.x = hz; h1.y = hw;
    l0.x = __float2bfloat16(v.x - __bfloat162float(hx));
    l0.y = __float2bfloat16(v.y - __bfloat162float(hy));
    l1.x = __float2bfloat16(v.z - __bfloat162float(hz));
    l1.y = __float2bfloat16(v.w - __bfloat162float(hw));
    *(__nv_bfloat162*)(hi)     = h0;
    *(__nv_bfloat162*)(hi + 2) = h1;
    *(__nv_bfloat162*)(lo)     = l0;
    *(__nv_bfloat162*)(lo + 2) = l1;
}

__global__ void cvt_split(const float* __restrict__ x,
                          __nv_bfloat16* __restrict__ hi,
                          __nv_bfloat16* __restrict__ lo, int n)
{
    int i = (blockIdx.x * blockDim.x + threadIdx.x) * 4;
    if (i >= n) return;
    split4(*(const float4*)(x + i), hi + i, lo + i);
}

__global__ void cvt_split_w4(const float* __restrict__ qw, const float* __restrict__ kw,
                             const float* __restrict__ vw, const float* __restrict__ gw,
                             __nv_bfloat16* __restrict__ hi, __nv_bfloat16* __restrict__ lo)
{
    int i = (blockIdx.x * blockDim.x + threadIdx.x) * 4;
    int row = i >> 11;
    int col = i & 2047;
    const float* src;
    if (row < 1024)      src = qw + (size_t)row * Dq + col;
    else if (row < 2048) src = kw + (size_t)(row - 1024) * Dq + col;
    else if (row < 4096) src = vw + (size_t)(row - 2048) * Dq + col;
    else                 src = gw + (size_t)(row - 4096) * Dq + col;
    split4(*(const float4*)src, hi + i, lo + i);
}

// ------------------------- a/b projections -> decay g and beta --------------
__device__ __forceinline__ float softplus_f(float x) {
    return fmaxf(x, 0.f) + log1pf(expf(-fabsf(x)));
}

__global__ void proj_ab_kernel(const float* __restrict__ h,
                               const float* __restrict__ a_w,
                               const float* __restrict__ b_w,
                               const float* __restrict__ A_log,
                               const float* __restrict__ dt_bias,
                               float* __restrict__ gd, float* __restrict__ bt)
{
    int w = (blockIdx.x * blockDim.x + threadIdx.x) >> 5;
    int lane = threadIdx.x & 31;
    if (w >= Mrows) return;
    const float* hr = h + (size_t)w * Dq;
    float acc[16];
#pragma unroll
    for (int p = 0; p < 16; p++) acc[p] = 0.f;
    for (int j = lane * 4; j < Dq; j += 128) {
        float4 hv = *(const float4*)(hr + j);
#pragma unroll
        for (int p = 0; p < 8; p++) {
            float4 av = *(const float4*)(a_w + (size_t)p * Dq + j);
            acc[p] += hv.x * av.x + hv.y * av.y + hv.z * av.z + hv.w * av.w;
            float4 bv = *(const float4*)(b_w + (size_t)p * Dq + j);
            acc[8 + p] += hv.x * bv.x + hv.y * bv.y + hv.z * bv.z + hv.w * bv.w;
        }
    }
#pragma unroll
    for (int p = 0; p < 16; p++)
#pragma unroll
        for (int m = 16; m; m >>= 1)
            acc[p] += __shfl_xor_sync(0xffffffffu, acc[p], m);

    if (lane < 8) {
        float x = acc[lane] + dt_bias[lane];
        gd[w * Hq + lane] = -expf(A_log[lane]) * softplus_f(x);
    } else if (lane < 16) {
        int p = lane - 8;
        bt[w * Hq + p] = 1.f / (1.f + expf(-acc[lane]));
    }
}

// ---------------- fused conv+SiLU+l2norm for q/k (head dim 128) -------------
__global__ void conv_l2_kernel(const float* __restrict__ P, int colofs,
                               const float* __restrict__ w, float* __restrict__ out)
{
    int gwp = (blockIdx.x * blockDim.x + threadIdx.x) >> 5;
    int lane = threadIdx.x & 31;
    int row = gwp >> 3, hh = gwp & 7;
    int t = row & (Tq - 1);
    int c = hh * 128 + lane * 4;
    const float* base = P + (size_t)row * NFUSE + colofs + c;
    float4 x0 = *(const float4*)base;
    float4 x1 = make_float4(0,0,0,0), x2 = x1, x3 = x1;
    if (t >= 1) x1 = *(const float4*)(base - NFUSE);
    if (t >= 2) x2 = *(const float4*)(base - 2*NFUSE);
    if (t >= 3) x3 = *(const float4*)(base - 3*NFUSE);
    float4 wc0 = *(const float4*)(w + (size_t)(c + 0) * 4);
    float4 wc1 = *(const float4*)(w + (size_t)(c + 1) * 4);
    float4 wc2 = *(const float4*)(w + (size_t)(c + 2) * 4);
    float4 wc3 = *(const float4*)(w + (size_t)(c + 3) * 4);
    float v0 = x0.x*wc0.w + x1.x*wc0.z + x2.x*wc0.y + x3.x*wc0.x;
    float v1 = x0.y*wc1.w + x1.y*wc1.z + x2.y*wc1.y + x3.y*wc1.x;
    float v2 = x0.z*wc2.w + x1.z*wc2.z + x2.z*wc2.y + x3.z*wc2.x;
    float v3 = x0.w*wc3.w + x1.w*wc3.z + x2.w*wc3.y + x3.w*wc3.x;
    v0 = v0 / (1.f + expf(-v0));
    v1 = v1 / (1.f + expf(-v1));
    v2 = v2 / (1.f + expf(-v2));
    v3 = v3 / (1.f + expf(-v3));
    float ss = v0*v0 + v1*v1 + v2*v2 + v3*v3;
#pragma unroll
    for (int m = 16; m; m >>= 1) ss += __shfl_xor_sync(0xffffffffu, ss, m);
    float r = rsqrtf(ss + 1e-6f);
    *(float4*)(out + (size_t)row * KDq + c) =
        make_float4(v0 * r, v1 * r, v2 * r, v3 * r);
}

// ---------------- conv+SiLU for v (elementwise, strided read) ---------------
__global__ void conv_silu_stride(const float* __restrict__ P, int colofs,
                                 const float* __restrict__ w, float* __restrict__ out)
{
    int i = blockIdx.x * blockDim.x + threadIdx.x;
    int c = i % VDq;
    int row = i / VDq;
    int t = row & (Tq - 1);
    const float* base = P + (size_t)row * NFUSE + colofs + c;
    float4 wc = *(const float4*)(w + (size_t)c * 4);
    float acc = base[0] * wc.w;
    if (t >= 1) acc += base[-1 * NFUSE] * wc.z;
    if (t >= 2) acc += base[-2 * NFUSE] * wc.y;
    if (t >= 3) acc += base[-3 * NFUSE] * wc.x;
    out[i] = acc / (1.f + expf(-acc));
}

// ======================= chunked gated delta-rule scan ======================
// K1: build A, blocked forward substitution for (I+A)[u_v|W] = [betaV | beta c K]
#define KSTR 132
#define K1_SMEM ((64*KSTR + 64*256 + 64*64 + 64*3 + 16)*4)

__global__ void __launch_bounds__(384) chunk_solve_kernel(
    const float* __restrict__ kc, const float* __restrict__ vc,
    const float* __restrict__ gd, const float* __restrict__ bt,
    float* __restrict__ uv, float* __restrict__ wm, float* __restrict__ clsg)
{
    extern __shared__ float sm[];
    float* ks  = sm;                 // [64][132]
    float* vs  = ks + 64*KSTR;       // [64][256]
    float* As  = vs + 64*256;        // [64][64]
    float* cls = As + 64*64;         // [64]
    float* bes = cls + 64;           // [64]
    float* ec  = bes + 64;           // [64]
    const int cu = blockIdx.x;
    const int ch = cu % NCH, bh = cu / NCH;
    const int h = bh % Hq, b = bh / Hq;
    const int row0 = b * Tq + ch * LCH;
    const int tid = threadIdx.x;

    for (int i = tid; i < 64*32; i += 384) {
        int t = i >> 5, f = (i & 31) * 4;
        *(float4*)(ks + t*KSTR + f) =
            *(const float4*)(kc + (size_t)(row0+t)*KDq + h*DKq + f);
    }
    for (int i = tid; i < 64*64; i += 384) {
        int t = i >> 6, f = (i & 63) * 4;
        *(float4*)(vs + t*256 + f) =
            *(const float4*)(vc + (size_t)(row0+t)*VDq + h*DVq + f);
    }
    if (tid < 64) bes[tid] = bt[(row0+tid)*Hq + h];
    if (tid == 0) {
        float a = 0.f;
        for (int t = 0; t < 64; t++) { a += gd[(row0+t)*Hq + h]; cls[t] = a; }
    }
    __syncthreads();
    if (tid < 64) { ec[tid] = expf(cls[tid]); clsg[cu*64 + tid] = cls[tid]; }
    __syncthreads();

    for (int p = tid; p < 64*64; p += 384) {
        int t = p >> 6, i = p & 63;
        float a = 0.f;
        if (i < t) {
            const float* kt = ks + t*KSTR;
            const float* ki = ks + i*KSTR;
            float d0=0.f,d1=0.f,d2=0.f,d3=0.f;
#pragma unroll 8
            for (int r = 0; r < 128; r += 4) {
                float4 x = *(const float4*)(kt + r);
                float4 y = *(const float4*)(ki + r);
                d0 += x.x*y.x; d1 += x.y*y.y; d2 += x.z*y.z; d3 += x.w*y.w;
            }
            a = bes[t] * expf(cls[t]-cls[i]) * ((d0+d1)+(d2+d3));
        }
        As[p] = a;
    }
    __syncthreads();

    // blocked forward substitution (8 blocks of 8)
    const int col = tid;   // 0..255 -> V cols, 256..383 -> K cols
    float xl[64];
#pragma unroll 1
    for (int jb = 0; jb < 8; jb++) {
        float acc[8];
#pragma unroll
        for (int r = 0; r < 8; r++) {
            int t = jb*8 + r;
            acc[r] = (col < 256) ? bes[t]*vs[t*256 + col]
                                 : bes[t]*ec[t]*ks[t*KSTR + (col-256)];
        }
#pragma unroll 1
        for (int i = 0; i < jb*8; i++) {
            float xi = xl[i];
#pragma unroll
            for (int r = 0; r < 8; r++)
                acc[r] -= As[(jb*8+r)*64 + i] * xi;
        }
#pragma unroll
        for (int r = 0; r < 8; r++) {
#pragma unroll
            for (int i2 = 0; i2 < r; i2++)
                acc[r] -= As[(jb*8+r)*64 + jb*8+i2] * acc[i2];
            xl[jb*8+r] = acc[r];
        }
        if (col < 256) {
#pragma unroll
            for (int r = 0; r < 8; r++)
                uv[((size_t)cu*64 + jb*8+r)*256 + col] = acc[r];
        } else {
#pragma unroll
            for (int r = 0; r < 8; r++)
                wm[((size_t)cu*64 + jb*8+r)*128 + (col-256)] = acc[r];
        }
    }
}

// K2: sequential over chunks; 256 CTAs (16 bh x 16 col-groups of 16 cols)
#define CGW 16
#define K2_SMEM ((128*CGW + 128*65 + 64*128 + 16*65 + 64 + 16)*4)

__global__ void __launch_bounds__(256) chunk_state_kernel(
    const float* __restrict__ kc, const float* __restrict__ wm,
    const float* __restrict__ uv, const float* __restrict__ clsg,
    float* __restrict__ ua, float* __restrict__ s0)
{
    extern __shared__ float sm[];
    float* Ssm = sm;                 // [128][16]
    float* Wt  = Ssm + 128*CGW;      // [128][65]  (W transposed, padded)
    float* ksm = Wt + 128*65;        // [64][128]
    float* Ut  = ksm + 64*128;       // [16][65]   (e*u transposed, padded)
    float* ets = Ut + 16*65;         // [64]
    const int cg = blockIdx.x, bh = blockIdx.y;
    const int h = bh & 7, b = bh >> 3;
    const int c0 = cg * CGW;
    const int tid = threadIdx.x;

    for (int i = tid; i < 128*CGW/4; i += 256)
        ((float4*)Ssm)[i] = make_float4(0.f, 0.f, 0.f, 0.f);
    __syncthreads();

    for (int ch = 0; ch < NCH; ch++) {
        const int cu = bh * NCH + ch;
        const int row0 = b * Tq + ch * LCH;
        const float clsL = clsg[cu*64 + 63];
        const float eL = expf(clsL);

        for (int i = tid; i < 2048; i += 256) {
            int t = i >> 5;
            int r4 = (i & 31) * 4;
            float4 wv = *(const float4*)(wm + (size_t)cu*8192 + t*128 + r4);
            Wt[(r4+0)*65 + t] = wv.x;
            Wt[(r4+1)*65 + t] = wv.y;
            Wt[(r4+2)*65 + t] = wv.z;
            Wt[(r4+3)*65 + t] = wv.w;
            *(float4*)(ksm + t*128 + r4) =
                *(const float4*)(kc + (size_t)(row0+t)*KDq + h*DKq + r4);
        }
        if (tid < 64) ets[tid] = expf(clsL - clsg[cu*64 + tid]);
        // store S0 (state before this chunk)
        for (int i = tid; i < 128*CGW/4; i += 256) {
            int r = (i*4) >> 4;
            int c = (i*4) & 15;
            *(float4*)(s0 + ((size_t)cu*128 + r)*256 + c0 + c) = ((float4*)Ssm)[i];
        }
        __syncthreads();

        // u = uv - W*S0 ; store ua ; Ut = e*u (transposed)
        {
            int t = tid & 63, cgrp = tid >> 6;
            int cb = cgrp * 4;
            float4 acc = *(const float4*)(uv + ((size_t)cu*64 + t)*256 + c0 + cb);
#pragma unroll 4
            for (int r = 0; r < 128; r++) {
                float w = Wt[r*65 + t];
                float4 s = *(const float4*)(Ssm + r*CGW + cb);
                acc.x -= w*s.x; acc.y -= w*s.y; acc.z -= w*s.z; acc.w -= w*s.w;
            }
            *(float4*)(ua + ((size_t)cu*64 + t)*256 + c0 + cb) = acc;
            float e = ets[t];
            Ut[(cb+0)*65 + t] = e*acc.x;
            Ut[(cb+1)*65 + t] = e*acc.y;
            Ut[(cb+2)*65 + t] = e*acc.z;
            Ut[(cb+3)*65 + t] = e*acc.w;
        }
        __syncthreads();

        // S = eL*S + k^T (e u)
        {
            int c = tid & 15, rq = tid >> 4;
            float acc[8];
#pragma unroll
            for (int j = 0; j < 8; j++)
                acc[j] = eL * Ssm[(rq*8+j)*CGW + c];
#pragma unroll 2
            for (int t = 0; t < 64; t++) {
                float u = Ut[c*65 + t];
                float4 k0 = *(const float4*)(ksm + t*128 + rq*8);
                float4 k1 = *(const float4*)(ksm + t*128 + rq*8 + 4);
                acc[0] += k0.x*u; acc[1] += k0.y*u; acc[2] += k0.z*u; acc[3] += k0.w*u;
                acc[4] += k1.x*u; acc[5] += k1.y*u; acc[6] += k1.z*u; acc[7] += k1.w*u;
            }
#pragma unroll
            for (int j = 0; j < 8; j++)
                Ssm[(rq*8+j)*CGW + c] = acc[j];
        }
        __syncthreads();
    }
}

// K3: outputs o_t = e^{cls_t} q_t^T S0 + sum_{i<=t} Gq[t,i] u_i (4 passes of 16)
#define K3_SMEM ((64*KSTR + 64*KSTR + 64*64 + 64*256 + 128 + 16)*4)

__global__ void __launch_bounds__(256) chunk_out_kernel(
    const float* __restrict__ qc, const float* __restrict__ kc,
    const float* __restrict__ ua, const float* __restrict__ s0,
    const float* __restrict__ clsg, float* __restrict__ o)
{
    extern __shared__ float sm[];
    float* qs  = sm;                 // [64][132]
    float* ks  = qs + 64*KSTR;       // [64][132]
    float* Gq  = ks + 64*KSTR;       // [64][64]
    float* uas = Gq + 64*64;         // [64][256]
    float* cls = uas + 64*256;       // [64]
    float* ecl = cls + 64;           // [64]
    const int cu = blockIdx.x;
    const int ch = cu % NCH, bh = cu / NCH;
    const int h = bh & 7, b = bh >> 3;
    const int row0 = b * Tq + ch * LCH;
    const int tid = threadIdx.x;

    for (int i = tid; i < 2048; i += 256) {
        int t = i >> 5, f = (i & 31) * 4;
        size_t go = (size_t)(row0+t)*KDq + h*DKq + f;
        *(float4*)(qs + t*KSTR + f) = *(const float4*)(qc + go);
        *(float4*)(ks + t*KSTR + f) = *(const float4*)(kc + go);
    }
    for (int i = tid; i < 4096; i += 256)
        *(float4*)(uas + i*4) = *(const float4*)(ua + (size_t)cu*16384 + i*4);
    if (tid < 64) cls[tid] = clsg[cu*64 + tid];
    __syncthreads();
    if (tid < 64) ecl[tid] = expf(cls[tid]);

    for (int p = tid; p < 64*64; p += 256) {
        int t = p >> 6, i = p & 63;
        float g = 0.f;
        if (i <= t) {
            const float* qt = qs + t*KSTR;
            const float* ki = ks + i*KSTR;
            float d0=0.f,d1=0.f,d2=0.f,d3=0.f;
#pragma unroll 8
            for (int r = 0; r < 128; r += 4) {
                float4 x = *(const float4*)(qt + r);
                float4 y = *(const float4*)(ki + r);
                d0 += x.x*y.x; d1 += x.y*y.y; d2 += x.z*y.z; d3 += x.w*y.w;
            }
            g = expf(cls[t]-cls[i]) * ((d0+d1)+(d2+d3));
        }
        Gq[p] = g;
    }
    __syncthreads();

    const int col = tid;
    const float scale = 0.08838834764831843f;
    const float* s0p = s0 + (size_t)cu*32768 + col;
#pragma unroll 1
    for (int pass = 0; pass < 4; pass++) {
        float acc[16];
#pragma unroll
        for (int j = 0; j < 16; j++) acc[j] = 0.f;
#pragma unroll 1
        for (int r = 0; r < 128; r += 4) {
            float4 sv;
            sv.x = s0p[(size_t)(r+0)*256];
            sv.y = s0p[(size_t)(r+1)*256];
            sv.z = s0p[(size_t)(r+2)*256];
            sv.w = s0p[(size_t)(r+3)*256];
#pragma unroll
            for (int j = 0; j < 16; j++) {
                float4 qv = *(const float4*)(qs + (pass*16+j)*KSTR + r);
                acc[j] += qv.x*sv.x + qv.y*sv.y + qv.z*sv.z + qv.w*sv.w;
            }
        }
#pragma unroll
        for (int j = 0; j < 16; j++) acc[j] *= ecl[pass*16+j];
#pragma unroll 1
        for (int i = 0; i < 64; i += 4) {
            float4 uvv;
            uvv.x = uas[(i+0)*256 + col];
            uvv.y = uas[(i+1)*256 + col];
            uvv.z = uas[(i+2)*256 + col];
            uvv.w = uas[(i+3)*256 + col];
#pragma unroll
            for (int j = 0; j < 16; j++) {
                float4 gv = *(const float4*)(Gq + (pass*16+j)*64 + i);
                acc[j] += gv.x*uvv.x + gv.y*uvv.y + gv.z*uvv.z + gv.w*uvv.w;
            }
        }
#pragma unroll
        for (int j = 0; j < 16; j++)
            o[(size_t)(row0 + pass*16+j)*VDq + h*DVq + col] = scale * acc[j];
    }
}

// ------------------------- gated RMSNorm -> bf16 hi/lo ----------------------
__global__ void rmsnorm_gate_kernel(const float* __restrict__ o,
                                    const float* __restrict__ P,
                                    const float* __restrict__ nw,
                                    __nv_bfloat16* __restrict__ oh,
                                    __nv_bfloat16* __restrict__ ol)
{
    int w = (blockIdx.x * blockDim.x + threadIdx.x) >> 5;
    int lane = threadIdx.x & 31;
    int row = w >> 3, hh = w & 7;
    const float* orow = o + (size_t)w * DVq;
    float4 o0 = *(const float4*)(orow + lane * 4);
    float4 o1 = *(const float4*)(orow + 128 + lane * 4);
    float ss = o0.x * o0.x + o0.y * o0.y + o0.z * o0.z + o0.w * o0.w
             + o1.x * o1.x + o1.y * o1.y + o1.z * o1.z + o1.w * o1.w;
#pragma unroll
    for (int m = 16; m; m >>= 1) ss += __shfl_xor_sync(0xffffffffu, ss, m);
    float r = rsqrtf(ss * (1.f / 256.f) + 1e-5f);
    const float* grow = P + (size_t)row * NFUSE + 4096 + hh * DVq;
    float4 g0 = *(const float4*)(grow + lane * 4);
    float4 g1 = *(const float4*)(grow + 128 + lane * 4);
    float4 w0 = *(const float4*)(nw + lane * 4);
    float4 w1 = *(const float4*)(nw + 128 + lane * 4);
    float f[8];
    f[0] = o0.x * r * w0.x * (g0.x / (1.f + expf(-g0.x)));
    f[1] = o0.y * r * w0.y * (g0.y / (1.f + expf(-g0.y)));
    f[2] = o0.z * r * w0.z * (g0.z / (1.f + expf(-g0.z)));
    f[3] = o0.w * r * w0.w * (g0.w / (1.f + expf(-g0.w)));
    f[4] = o1.x * r * w1.x * (g1.x / (1.f + expf(-g1.x)));
    f[5] = o1.y * r * w1.y * (g1.y / (1.f + expf(-g1.y)));
    f[6] = o1.z * r * w1.z * (g1.z / (1.f + expf(-g1.z)));
    f[7] = o1.w * r * w1.w * (g1.w / (1.f + expf(-g1.w)));
#pragma unroll
    for (int half = 0; half < 2; half++) {
        size_t base = (size_t)w * DVq + half * 128 + lane * 4;
        float a = f[half*4+0], b2 = f[half*4+1], c = f[half*4+2], d = f[half*4+3];
        split4(make_float4(a, b2, c, d), oh + base, ol + base);
    }
}

// ------------------------- launch -------------------------------------------
extern "C" void kernel_launch(void* const* d_in, const int* in_sizes, int n_in,
                              void* d_out, int out_size)
{
    const float* h        = (const float*)d_in[0];
    const float* q_w      = (const float*)d_in[1];
    const float* k_w      = (const float*)d_in[2];
    const float* v_w      = (const float*)d_in[3];
    const float* a_w      = (const float*)d_in[4];
    const float* b_w      = (const float*)d_in[5];
    const float* g_w      = (const float*)d_in[6];
    const float* o_w      = (const float*)d_in[7];
    const float* q_conv_w = (const float*)d_in[8];
    const float* k_conv_w = (const float*)d_in[9];
    const float* v_conv_w = (const float*)d_in[10];
    const float* A_log    = (const float*)d_in[11];
    const float* dt_bias  = (const float*)d_in[12];
    const float* o_norm_w = (const float*)d_in[13];
    float* out = (float*)d_out;

    float *P, *qc, *kc, *vc, *gd, *bt, *orow;
    float *cls, *uv, *wmp, *uap, *s0p;
    cudaGetSymbolAddress((void**)&P, g_proj);
    cudaGetSymbolAddress((void**)&qc, g_qc);
    cudaGetSymbolAddress((void**)&kc, g_kc);
    cudaGetSymbolAddress((void**)&vc, g_vc);
    cudaGetSymbolAddress((void**)&gd, g_gd);
    cudaGetSymbolAddress((void**)&bt, g_bt);
    cudaGetSymbolAddress((void**)&orow, g_orow);
    cudaGetSymbolAddress((void**)&cls, g_cls);
    cudaGetSymbolAddress((void**)&uv, g_uv);
    cudaGetSymbolAddress((void**)&wmp, g_wm);
    cudaGetSymbolAddress((void**)&uap, g_ua);
    cudaGetSymbolAddress((void**)&s0p, g_s0);

    __nv_bfloat16 *hh, *hl, *wh, *wl, *owh, *owl, *onh, *onl;
    cudaGetSymbolAddress((void**)&hh, g_hh);   cudaGetSymbolAddress((void**)&hl, g_hl);
    cudaGetSymbolAddress((void**)&wh, g_wh);   cudaGetSymbolAddress((void**)&wl, g_wl);
    cudaGetSymbolAddress((void**)&owh, g_owh); cudaGetSymbolAddress((void**)&owl, g_owl);
    cudaGetSymbolAddress((void**)&onh, g_onh); cudaGetSymbolAddress((void**)&onl, g_onl);

    cudaFuncSetAttribute(bgemm_nt_split, cudaFuncAttributeMaxDynamicSharedMemorySize, SMEM_GEMM);
    cudaFuncSetAttribute(chunk_solve_kernel, cudaFuncAttributeMaxDynamicSharedMemorySize, K1_SMEM);
    cudaFuncSetAttribute(chunk_state_kernel, cudaFuncAttributeMaxDynamicSharedMemorySize, K2_SMEM);
    cudaFuncSetAttribute(chunk_out_kernel,   cudaFuncAttributeMaxDynamicSharedMemorySize, K3_SMEM);

    // 0) bf16 hi/lo splits
    cvt_split<<<(Mrows*Dq/4 + 255)/256, 256>>>(h, hh, hl, Mrows*Dq);
    cvt_split_w4<<<(NFUSE*Dq/4 + 255)/256, 256>>>(q_w, k_w, v_w, g_w, wh, wl);
    cvt_split<<<(Dq*VDq/4 + 255)/256, 256>>>(o_w, owh, owl, Dq*VDq);

    // 1) fused q|k|v|gate projection on tensor cores
    bgemm_nt_split<<<dim3(NFUSE/128, Mrows/128), 256, SMEM_GEMM>>>(hh, hl, wh, wl, P, NFUSE);

    // 2) a/b projections -> decay + beta
    proj_ab_kernel<<<(Mrows * 32) / 256, 256>>>(h, a_w, b_w, A_log, dt_bias, gd, bt);

    // 3) conv+SiLU+l2norm for q,k ; conv+SiLU for v
    conv_l2_kernel<<<(Mrows * Hq * 32) / 256, 256>>>(P, 0,    q_conv_w, qc);
    conv_l2_kernel<<<(Mrows * Hq * 32) / 256, 256>>>(P, 1024, k_conv_w, kc);
    conv_silu_stride<<<(Mrows * VDq) / 256, 256>>>(P, 2048, v_conv_w, vc);

    // 4) chunked gated delta-rule scan
    chunk_solve_kernel<<<NU, 384, K1_SMEM>>>(kc, vc, gd, bt, uv, wmp, cls);
    chunk_state_kernel<<<dim3(16, Bq*Hq), 256, K2_SMEM>>>(kc, wmp, uv, cls, uap, s0p);
    chunk_out_kernel<<<NU, 256, K3_SMEM>>>(qc, kc, uap, s0p, cls, orow);

    // 5) gated RMSNorm (+ bf16 hi/lo split)
    rmsnorm_gate_kernel<<<(Mrows * Hq * 32) / 256, 256>>>(orow, P, o_norm_w, onh, onl);

    // 6) output projection -> d_out
    bgemm_nt_split<<<dim3(Dq/128, Mrows/128), 256, SMEM_GEMM>>>(onh, onl, owh, owl, out, Dq);
}

// round 10
// speedup vs baseline: 1.2080x; 1.0017x over previous
#include <cuda_runtime.h>
#include <cuda_bf16.h>
#include <math.h>
#include <stdint.h>

#define Bq 2
#define Tq 1024
#define Dq 2048
#define Hq 8
#define DKq 128
#define DVq 256
#define KDq 1024
#define VDq 2048
#define Mrows (Bq*Tq)   // 2048
#define GK 2048         // K for every big GEMM
#define NFUSE 6144      // q(1024) + k(1024) + v(2048) + gate(2048)
#define LCH 64          // scan chunk length
#define NCH (Tq/LCH)    // 16 chunks per sequence
#define NU  (Bq*Hq*NCH) // 256 chunk units

// ------------------------- scratch (device globals) -------------------------
__device__ float g_proj[Mrows*NFUSE];
__device__ float g_qc[Mrows*KDq];
__device__ float g_kc[Mrows*KDq];
__device__ float g_vc[Mrows*VDq];
__device__ float g_gd[Mrows*Hq];
__device__ float g_bt[Mrows*Hq];
__device__ float g_orow[Mrows*VDq];

// chunked-scan intermediates
__device__ float g_cls[NU*LCH];
__device__ float g_uv [NU*LCH*DVq];
__device__ float g_wm [NU*LCH*DKq];
__device__ float g_ua [NU*LCH*DVq];
__device__ float g_s0 [NU*DKq*DVq];

// bf16 split (hi/lo) operands
__device__ __nv_bfloat16 g_hh[Mrows*Dq],    g_hl[Mrows*Dq];
__device__ __nv_bfloat16 g_wh[NFUSE*Dq],    g_wl[NFUSE*Dq];
__device__ __nv_bfloat16 g_owh[Dq*VDq],     g_owl[Dq*VDq];
__device__ __nv_bfloat16 g_onh[Mrows*VDq],  g_onl[Mrows*VDq];

// ------------------------- helpers ------------------------------------------
__device__ __forceinline__ uint32_t smem_u32(const void* p) {
    uint32_t a;
    asm("{ .reg .u64 t; cvta.to.shared.u64 t, %1; cvt.u32.u64 %0, t; }" : "=r"(a) : "l"(p));
    return a;
}
__device__ __forceinline__ void cp16(uint32_t dst, const void* src) {
    asm volatile("cp.async.cg.shared.global [%0], [%1], 16;" :: "r"(dst), "l"(src));
}
__device__ __forceinline__ void cp_commit() {
    asm volatile("cp.async.commit_group;" ::: "memory");
}
template <int N>
__device__ __forceinline__ void cp_wait() {
    asm volatile("cp.async.wait_group %0;" :: "n"(N) : "memory");
}
__device__ __forceinline__ void ldsm_x4(uint32_t addr, uint32_t* r) {
    asm volatile("ldmatrix.sync.aligned.m8n8.x4.shared.b16 {%0,%1,%2,%3}, [%4];"
                 : "=r"(r[0]), "=r"(r[1]), "=r"(r[2]), "=r"(r[3]) : "r"(addr));
}
__device__ __forceinline__ void mma_bf16(float* c, const uint32_t* a, const uint32_t* b) {
    asm volatile(
        "mma.sync.aligned.m16n8k16.row.col.f32.bf16.bf16.f32 "
        "{%0,%1,%2,%3}, {%4,%5,%6,%7}, {%8,%9}, {%0,%1,%2,%3};"
        : "+f"(c[0]), "+f"(c[1]), "+f"(c[2]), "+f"(c[3])
        : "r"(a[0]), "r"(a[1]), "r"(a[2]), "r"(a[3]), "r"(b[0]), "r"(b[1]));
}

// ------------------------- split bf16 HMMA GEMM (2-stage, 2 CTA/SM) ---------
#define ROWB 80
#define MATB (128*ROWB)
#define STGB (4*MATB)
#define SMEM_GEMM (2*STGB)

__global__ void __launch_bounds__(256, 2) bgemm_nt_split(
    const __nv_bfloat16* __restrict__ Ah, const __nv_bfloat16* __restrict__ Al,
    const __nv_bfloat16* __restrict__ Bh, const __nv_bfloat16* __restrict__ Bl,
    float* __restrict__ C, int N)
{
    extern __shared__ char smem[];
    const uint32_t sb = smem_u32(smem);
    const int tid = threadIdx.x, wid = tid >> 5, lane = tid & 31;
    const int bm = blockIdx.y * 128, bn = blockIdx.x * 128;
    const int wm = (wid >> 1) * 32;
    const int wn = (wid & 1) * 64;

    float acc[2][8][4];
#pragma unroll
    for (int i = 0; i < 2; i++)
#pragma unroll
        for (int j = 0; j < 8; j++)
#pragma unroll
            for (int l = 0; l < 4; l++) acc[i][j][l] = 0.f;

    const int NC = GK / 32;

#define PREFETCH(cc, ss)                                                          \
    {                                                                             \
        const int kc = (cc) * 32;                                                 \
        const uint32_t stg = sb + (uint32_t)(ss) * STGB;                          \
        _Pragma("unroll")                                                         \
        for (int i = 0; i < 2; i++) {                                             \
            int idx = tid + i * 256;                                              \
            int row = idx >> 2, seg = idx & 3;                                    \
            uint32_t so = (uint32_t)(row * ROWB + seg * 16);                      \
            size_t ea = (size_t)(bm + row) * GK + kc + seg * 8;                   \
            size_t eb = (size_t)(bn + row) * GK + kc + seg * 8;                   \
            cp16(stg + so,            Ah + ea);                                   \
            cp16(stg + MATB + so,     Al + ea);                                   \
            cp16(stg + 2*MATB + so,   Bh + eb);                                   \
            cp16(stg + 3*MATB + so,   Bl + eb);                                   \
        }                                                                         \
        cp_commit();                                                              \
    }

    PREFETCH(0, 0);
    PREFETCH(1, 1);

    const uint32_t a_row = (uint32_t)(wm + (lane & 15));
    const uint32_t a_colb = (uint32_t)((lane >> 4) * 16);
    const uint32_t b_row0 = (uint32_t)(wn + (lane & 7) + ((lane >> 4) << 3));
    const uint32_t b_colb = (uint32_t)(((lane >> 3) & 1) * 16);

    for (int c = 0; c < NC; c++) {
        if (c == NC - 1) cp_wait<0>(); else cp_wait<1>();
        __syncthreads();
        const uint32_t stg = sb + (uint32_t)(c & 1) * STGB;

#pragma unroll
        for (int k16 = 0; k16 < 2; k16++) {
            const uint32_t kb = (uint32_t)(k16 * 32);
            uint32_t a0[2][4], a1[2][4], bb[4][4];

#pragma unroll
            for (int mt = 0; mt < 2; mt++) {
                uint32_t ao = (a_row + mt * 16) * ROWB + kb + a_colb;
                ldsm_x4(stg + ao, a0[mt]);
            }
#pragma unroll
            for (int np = 0; np < 4; np++) {
                uint32_t bo = (b_row0 + np * 16) * ROWB + kb + b_colb;
                ldsm_x4(stg + 2*MATB + bo, bb[np]);
            }
#pragma unroll
            for (int mt = 0; mt < 2; mt++)
#pragma unroll
                for (int np = 0; np < 4; np++) {
                    mma_bf16(acc[mt][np*2],   a0[mt], bb[np]);
                    mma_bf16(acc[mt][np*2+1], a0[mt], bb[np] + 2);
                }

#pragma unroll
            for (int mt = 0; mt < 2; mt++) {
                uint32_t ao = (a_row + mt * 16) * ROWB + kb + a_colb;
                ldsm_x4(stg + MATB + ao, a1[mt]);
            }
#pragma unroll
            for (int mt = 0; mt < 2; mt++)
#pragma unroll
                for (int np = 0; np < 4; np++) {
                    mma_bf16(acc[mt][np*2],   a1[mt], bb[np]);
                    mma_bf16(acc[mt][np*2+1], a1[mt], bb[np] + 2);
                }

#pragma unroll
            for (int np = 0; np < 4; np++) {
                uint32_t bo = (b_row0 + np * 16) * ROWB + kb + b_colb;
                ldsm_x4(stg + 3*MATB + bo, bb[np]);
            }
#pragma unroll
            for (int mt = 0; mt < 2; mt++)
#pragma unroll
                for (int np = 0; np < 4; np++) {
                    mma_bf16(acc[mt][np*2],   a0[mt], bb[np]);
                    mma_bf16(acc[mt][np*2+1], a0[mt], bb[np] + 2);
                }
        }
        __syncthreads();
        if (c + 2 < NC) PREFETCH(c + 2, c & 1);
    }
#undef PREFETCH

#pragma unroll
    for (int mt = 0; mt < 2; mt++) {
        int r0 = bm + wm + mt * 16 + (lane >> 2);
#pragma unroll
        for (int nt = 0; nt < 8; nt++) {
            int col = bn + wn + nt * 8 + (lane & 3) * 2;
            float2 v0 = make_float2(acc[mt][nt][0], acc[mt][nt][1]);
            float2 v1 = make_float2(acc[mt][nt][2], acc[mt][nt][3]);
            *(float2*)(C + (size_t)r0 * N + col)       = v0;
            *(float2*)(C + (size_t)(r0 + 8) * N + col) = v1;
        }
    }
}

// ------------------------- fp32 -> bf16 hi/lo split -------------------------
__device__ __forceinline__ void split4(float4 v, __nv_bfloat16* hi, __nv_bfloat16* lo) {
    __nv_bfloat16 hx = __float2bfloat16(v.x), hy = __float2bfloat16(v.y);
    __nv_bfloat16 hz = __float2bfloat16(v.z), hw = __float2bfloat16(v.w);
    __nv_bfloat162 h0, h1, l0, l1;
    h0.x = hx; h0.y = hy; h1.x = hz; h1.y = hw;
    l0.x = __float2bfloat16(v.x - __bfloat162float(hx));
    l0.y = __float2bfloat16(v.y - __bfloat162float(hy));
    l1.x = __float2bfloat16(v.z - __bfloat162float(hz));
    l1.y = __float2bfloat16(v.w - __bfloat162float(hw));
    *(__nv_bfloat162*)(hi)     = h0;
    *(__nv_bfloat162*)(hi + 2) = h1;
    *(__nv_bfloat162*)(lo)     = l0;
    *(__nv_bfloat162*)(lo + 2) = l1;
}

__global__ void cvt_split(const float* __restrict__ x,
                          __nv_bfloat16* __restrict__ hi,
                          __nv_bfloat16* __restrict__ lo, int n)
{
    int i = (blockIdx.x * blockDim.x + threadIdx.x) * 4;
    if (i >= n) return;
    split4(*(const float4*)(x + i), hi + i, lo + i);
}

__global__ void cvt_split_w4(const float* __restrict__ qw, const float* __restrict__ kw,
                             const float* __restrict__ vw, const float* __restrict__ gw,
                             __nv_bfloat16* __restrict__ hi, __nv_bfloat16* __restrict__ lo)
{
    int i = (blockIdx.x * blockDim.x + threadIdx.x) * 4;
    int row = i >> 11;
    int col = i & 2047;
    const float* src;
    if (row < 1024)      src = qw + (size_t)row * Dq + col;
    else if (row < 2048) src = kw + (size_t)(row - 1024) * Dq + col;
    else if (row < 4096) src = vw + (size_t)(row - 2048) * Dq + col;
    else                 src = gw + (size_t)(row - 4096) * Dq + col;
    split4(*(const float4*)src, hi + i, lo + i);
}

// ------------------------- a/b projections -> decay g and beta --------------
__device__ __forceinline__ float softplus_f(float x) {
    return fmaxf(x, 0.f) + log1pf(expf(-fabsf(x)));
}

__global__ void proj_ab_kernel(const float* __restrict__ h,
                               const float* __restrict__ a_w,
                               const float* __restrict__ b_w,
                               const float* __restrict__ A_log,
                               const float* __restrict__ dt_bias,
                               float* __restrict__ gd, float* __restrict__ bt)
{
    int w = (blockIdx.x * blockDim.x + threadIdx.x) >> 5;
    int lane = threadIdx.x & 31;
    if (w >= Mrows) return;
    const float* hr = h + (size_t)w * Dq;
    float acc[16];
#pragma unroll
    for (int p = 0; p < 16; p++) acc[p] = 0.f;
    for (int j = lane * 4; j < Dq; j += 128) {
        float4 hv = *(const float4*)(hr + j);
#pragma unroll
        for (int p = 0; p < 8; p++) {
            float4 av = *(const float4*)(a_w + (size_t)p * Dq + j);
            acc[p] += hv.x * av.x + hv.y * av.y + hv.z * av.z + hv.w * av.w;
            float4 bv = *(const float4*)(b_w + (size_t)p * Dq + j);
            acc[8 + p] += hv.x * bv.x + hv.y * bv.y + hv.z * bv.z + hv.w * bv.w;
        }
    }
#pragma unroll
    for (int p = 0; p < 16; p++)
#pragma unroll
        for (int m = 16; m; m >>= 1)
            acc[p] += __shfl_xor_sync(0xffffffffu, acc[p], m);

    if (lane < 8) {
        float x = acc[lane] + dt_bias[lane];
        gd[w * Hq + lane] = -expf(A_log[lane]) * softplus_f(x);
    } else if (lane < 16) {
        int p = lane - 8;
        bt[w * Hq + p] = 1.f / (1.f + expf(-acc[lane]));
    }
}

// ---------------- fused conv+SiLU+l2norm for q/k (head dim 128) -------------
__global__ void conv_l2_kernel(const float* __restrict__ P, int colofs,
                               const float* __restrict__ w, float* __restrict__ out)
{
    int gwp = (blockIdx.x * blockDim.x + threadIdx.x) >> 5;
    int lane = threadIdx.x & 31;
    int row = gwp >> 3, hh = gwp & 7;
    int t = row & (Tq - 1);
    int c = hh * 128 + lane * 4;
    const float* base = P + (size_t)row * NFUSE + colofs + c;
    float4 x0 = *(const float4*)base;
    float4 x1 = make_float4(0,0,0,0), x2 = x1, x3 = x1;
    if (t >= 1) x1 = *(const float4*)(base - NFUSE);
    if (t >= 2) x2 = *(const float4*)(base - 2*NFUSE);
    if (t >= 3) x3 = *(const float4*)(base - 3*NFUSE);
    float4 wc0 = *(const float4*)(w + (size_t)(c + 0) * 4);
    float4 wc1 = *(const float4*)(w + (size_t)(c + 1) * 4);
    float4 wc2 = *(const float4*)(w + (size_t)(c + 2) * 4);
    float4 wc3 = *(const float4*)(w + (size_t)(c + 3) * 4);
    float v0 = x0.x*wc0.w + x1.x*wc0.z + x2.x*wc0.y + x3.x*wc0.x;
    float v1 = x0.y*wc1.w + x1.y*wc1.z + x2.y*wc1.y + x3.y*wc1.x;
    float v2 = x0.z*wc2.w + x1.z*wc2.z + x2.z*wc2.y + x3.z*wc2.x;
    float v3 = x0.w*wc3.w + x1.w*wc3.z + x2.w*wc3.y + x3.w*wc3.x;
    v0 = v0 / (1.f + expf(-v0));
    v1 = v1 / (1.f + expf(-v1));
    v2 = v2 / (1.f + expf(-v2));
    v3 = v3 / (1.f + expf(-v3));
    float ss = v0*v0 + v1*v1 + v2*v2 + v3*v3;
#pragma unroll
    for (int m = 16; m; m >>= 1) ss += __shfl_xor_sync(0xffffffffu, ss, m);
    float r = rsqrtf(ss + 1e-6f);
    *(float4*)(out + (size_t)row * KDq + c) =
        make_float4(v0 * r, v1 * r, v2 * r, v3 * r);
}

// ---------------- conv+SiLU for v (elementwise, strided read) ---------------
__global__ void conv_silu_stride(const float* __restrict__ P, int colofs,
                                 const float* __restrict__ w, float* __restrict__ out)
{
    int i = blockIdx.x * blockDim.x + threadIdx.x;
    int c = i % VDq;
    int row = i / VDq;
    int t = row & (Tq - 1);
    const float* base = P + (size_t)row * NFUSE + colofs + c;
    float4 wc = *(const float4*)(w + (size_t)c * 4);
    float acc = base[0] * wc.w;
    if (t >= 1) acc += base[-1 * NFUSE] * wc.z;
    if (t >= 2) acc += base[-2 * NFUSE] * wc.y;
    if (t >= 3) acc += base[-3 * NFUSE] * wc.x;
    out[i] = acc / (1.f + expf(-acc));
}

// ======================= chunked gated delta-rule scan ======================
// K1: build A, blocked forward substitution for (I+A)[u_v|W] = [betaV | beta c K]
#define KSTR 132
#define K1_SMEM ((64*KSTR + 64*256 + 64*64 + 64*3 + 16)*4)

__global__ void __launch_bounds__(384) chunk_solve_kernel(
    const float* __restrict__ kc, const float* __restrict__ vc,
    const float* __restrict__ gd, const float* __restrict__ bt,
    float* __restrict__ uv, float* __restrict__ wm, float* __restrict__ clsg)
{
    extern __shared__ float sm[];
    float* ks  = sm;                 // [64][132]
    float* vs  = ks + 64*KSTR;       // [64][256]
    float* As  = vs + 64*256;        // [64][64]
    float* cls = As + 64*64;         // [64]
    float* bes = cls + 64;           // [64]
    float* ec  = bes + 64;           // [64]
    const int cu = blockIdx.x;
    const int ch = cu % NCH, bh = cu / NCH;
    const int h = bh % Hq, b = bh / Hq;
    const int row0 = b * Tq + ch * LCH;
    const int tid = threadIdx.x;

    for (int i = tid; i < 64*32; i += 384) {
        int t = i >> 5, f = (i & 31) * 4;
        *(float4*)(ks + t*KSTR + f) =
            *(const float4*)(kc + (size_t)(row0+t)*KDq + h*DKq + f);
    }
    for (int i = tid; i < 64*64; i += 384) {
        int t = i >> 6, f = (i & 63) * 4;
        *(float4*)(vs + t*256 + f) =
            *(const float4*)(vc + (size_t)(row0+t)*VDq + h*DVq + f);
    }
    if (tid < 64) bes[tid] = bt[(row0+tid)*Hq + h];
    if (tid == 0) {
        float a = 0.f;
        for (int t = 0; t < 64; t++) { a += gd[(row0+t)*Hq + h]; cls[t] = a; }
    }
    __syncthreads();
    if (tid < 64) { ec[tid] = expf(cls[tid]); clsg[cu*64 + tid] = cls[tid]; }
    __syncthreads();

    for (int p = tid; p < 64*64; p += 384) {
        int t = p >> 6, i = p & 63;
        float a = 0.f;
        if (i < t) {
            const float* kt = ks + t*KSTR;
            const float* ki = ks + i*KSTR;
            float d0=0.f,d1=0.f,d2=0.f,d3=0.f;
#pragma unroll 8
            for (int r = 0; r < 128; r += 4) {
                float4 x = *(const float4*)(kt + r);
                float4 y = *(const float4*)(ki + r);
                d0 += x.x*y.x; d1 += x.y*y.y; d2 += x.z*y.z; d3 += x.w*y.w;
            }
            a = bes[t] * expf(cls[t]-cls[i]) * ((d0+d1)+(d2+d3));
        }
        As[p] = a;
    }
    __syncthreads();

    // blocked forward substitution (8 blocks of 8)
    const int col = tid;   // 0..255 -> V cols, 256..383 -> K cols
    float xl[64];
#pragma unroll 1
    for (int jb = 0; jb < 8; jb++) {
        float acc[8];
#pragma unroll
        for (int r = 0; r < 8; r++) {
            int t = jb*8 + r;
            acc[r] = (col < 256) ? bes[t]*vs[t*256 + col]
                                 : bes[t]*ec[t]*ks[t*KSTR + (col-256)];
        }
#pragma unroll 1
        for (int i = 0; i < jb*8; i++) {
            float xi = xl[i];
#pragma unroll
            for (int r = 0; r < 8; r++)
                acc[r] -= As[(jb*8+r)*64 + i] * xi;
        }
#pragma unroll
        for (int r = 0; r < 8; r++) {
#pragma unroll
            for (int i2 = 0; i2 < r; i2++)
                acc[r] -= As[(jb*8+r)*64 + jb*8+i2] * acc[i2];
            xl[jb*8+r] = acc[r];
        }
        if (col < 256) {
#pragma unroll
            for (int r = 0; r < 8; r++)
                uv[((size_t)cu*64 + jb*8+r)*256 + col] = acc[r];
        } else {
#pragma unroll
            for (int r = 0; r < 8; r++)
                wm[((size_t)cu*64 + jb*8+r)*128 + (col-256)] = acc[r];
        }
    }
}

// K2: sequential over chunks; 256 CTAs (16 bh x 16 col-groups of 16 cols)
#define CGW 16
#define K2_SMEM ((128*CGW + 128*65 + 64*128 + 16*65 + 64 + 16)*4)

__global__ void __launch_bounds__(256) chunk_state_kernel(
    const float* __restrict__ kc, const float* __restrict__ wm,
    const float* __restrict__ uv, const float* __restrict__ clsg,
    float* __restrict__ ua, float* __restrict__ s0)
{
    extern __shared__ float sm[];
    float* Ssm = sm;                 // [128][16]
    float* Wt  = Ssm + 128*CGW;      // [128][65]  (W transposed, padded)
    float* ksm = Wt + 128*65;        // [64][128]
    float* Ut  = ksm + 64*128;       // [16][65]   (e*u transposed, padded)
    float* ets = Ut + 16*65;         // [64]
    const int cg = blockIdx.x, bh = blockIdx.y;
    const int h = bh & 7, b = bh >> 3;
    const int c0 = cg * CGW;
    const int tid = threadIdx.x;

    for (int i = tid; i < 128*CGW/4; i += 256)
        ((float4*)Ssm)[i] = make_float4(0.f, 0.f, 0.f, 0.f);
    __syncthreads();

    for (int ch = 0; ch < NCH; ch++) {
        const int cu = bh * NCH + ch;
        const int row0 = b * Tq + ch * LCH;
        const float clsL = clsg[cu*64 + 63];
        const float eL = expf(clsL);

        for (int i = tid; i < 2048; i += 256) {
            int t = i >> 5;
            int r4 = (i & 31) * 4;
            float4 wv = *(const float4*)(wm + (size_t)cu*8192 + t*128 + r4);
            Wt[(r4+0)*65 + t] = wv.x;
            Wt[(r4+1)*65 + t] = wv.y;
            Wt[(r4+2)*65 + t] = wv.z;
            Wt[(r4+3)*65 + t] = wv.w;
            *(float4*)(ksm + t*128 + r4) =
                *(const float4*)(kc + (size_t)(row0+t)*KDq + h*DKq + r4);
        }
        if (tid < 64) ets[tid] = expf(clsL - clsg[cu*64 + tid]);
        // store S0 (state before this chunk)
        for (int i = tid; i < 128*CGW/4; i += 256) {
            int r = (i*4) >> 4;
            int c = (i*4) & 15;
            *(float4*)(s0 + ((size_t)cu*128 + r)*256 + c0 + c) = ((float4*)Ssm)[i];
        }
        __syncthreads();

        // u = uv - W*S0 ; store ua ; Ut = e*u (transposed)
        {
            int t = tid & 63, cgrp = tid >> 6;
            int cb = cgrp * 4;
            float4 acc = *(const float4*)(uv + ((size_t)cu*64 + t)*256 + c0 + cb);
#pragma unroll 4
            for (int r = 0; r < 128; r++) {
                float w = Wt[r*65 + t];
                float4 s = *(const float4*)(Ssm + r*CGW + cb);
                acc.x -= w*s.x; acc.y -= w*s.y; acc.z -= w*s.z; acc.w -= w*s.w;
            }
            *(float4*)(ua + ((size_t)cu*64 + t)*256 + c0 + cb) = acc;
            float e = ets[t];
            Ut[(cb+0)*65 + t] = e*acc.x;
            Ut[(cb+1)*65 + t] = e*acc.y;
            Ut[(cb+2)*65 + t] = e*acc.z;
            Ut[(cb+3)*65 + t] = e*acc.w;
        }
        __syncthreads();

        // S = eL*S + k^T (e u)
        {
            int c = tid & 15, rq = tid >> 4;
            float acc[8];
#pragma unroll
            for (int j = 0; j < 8; j++)
                acc[j] = eL * Ssm[(rq*8+j)*CGW + c];
#pragma unroll 2
            for (int t = 0; t < 64; t++) {
                float u = Ut[c*65 + t];
                float4 k0 = *(const float4*)(ksm + t*128 + rq*8);
                float4 k1 = *(const float4*)(ksm + t*128 + rq*8 + 4);
                acc[0] += k0.x*u; acc[1] += k0.y*u; acc[2] += k0.z*u; acc[3] += k0.w*u;
                acc[4] += k1.x*u; acc[5] += k1.y*u; acc[6] += k1.z*u; acc[7] += k1.w*u;
            }
#pragma unroll
            for (int j = 0; j < 8; j++)
                Ssm[(rq*8+j)*CGW + c] = acc[j];
        }
        __syncthreads();
    }
}

// K3: outputs o_t = e^{cls_t} q_t^T S0 + sum_{i<=t} Gq[t,i] u_i (4 passes of 16)
#define K3_SMEM ((64*KSTR + 64*KSTR + 64*64 + 64*256 + 128 + 16)*4)

__global__ void __launch_bounds__(256) chunk_out_kernel(
    const float* __restrict__ qc, const float* __restrict__ kc,
    const float* __restrict__ ua, const float* __restrict__ s0,
    const float* __restrict__ clsg, float* __restrict__ o)
{
    extern __shared__ float sm[];
    float* qs  = sm;                 // [64][132]
    float* ks  = qs + 64*KSTR;       // [64][132]
    float* Gq  = ks + 64*KSTR;       // [64][64]
    float* uas = Gq + 64*64;         // [64][256]
    float* cls = uas + 64*256;       // [64]
    float* ecl = cls + 64;           // [64]
    const int cu = blockIdx.x;
    const int ch = cu % NCH, bh = cu / NCH;
    const int h = bh & 7, b = bh >> 3;
    const int row0 = b * Tq + ch * LCH;
    const int tid = threadIdx.x;

    for (int i = tid; i < 2048; i += 256) {
        int t = i >> 5, f = (i & 31) * 4;
        size_t go = (size_t)(row0+t)*KDq + h*DKq + f;
        *(float4*)(qs + t*KSTR + f) = *(const float4*)(qc + go);
        *(float4*)(ks + t*KSTR + f) = *(const float4*)(kc + go);
    }
    for (int i = tid; i < 4096; i += 256)
        *(float4*)(uas + i*4) = *(const float4*)(ua + (size_t)cu*16384 + i*4);
    if (tid < 64) cls[tid] = clsg[cu*64 + tid];
    __syncthreads();
    if (tid < 64) ecl[tid] = expf(cls[tid]);

    for (int p = tid; p < 64*64; p += 256) {
        int t = p >> 6, i = p & 63;
        float g = 0.f;
        if (i <= t) {
            const float* qt = qs + t*KSTR;
            const float* ki = ks + i*KSTR;
            float d0=0.f,d1=0.f,d2=0.f,d3=0.f;
#pragma unroll 8
            for (int r = 0; r < 128; r += 4) {
                float4 x = *(const float4*)(qt + r);
                float4 y = *(const float4*)(ki + r);
                d0 += x.x*y.x; d1 += x.y*y.y; d2 += x.z*y.z; d3 += x.w*y.w;
            }
            g = expf(cls[t]-cls[i]) * ((d0+d1)+(d2+d3));
        }
        Gq[p] = g;
    }
    __syncthreads();

    const int col = tid;
    const float scale = 0.08838834764831843f;
    const float* s0p = s0 + (size_t)cu*32768 + col;
#pragma unroll 1
    for (int pass = 0; pass < 4; pass++) {
        float acc[16];
#pragma unroll
        for (int j = 0; j < 16; j++) acc[j] = 0.f;
#pragma unroll 1
        for (int r = 0; r < 128; r += 4) {
            float4 sv;
            sv.x = s0p[(size_t)(r+0)*256];
            sv.y = s0p[(size_t)(r+1)*256];
            sv.z = s0p[(size_t)(r+2)*256];
            sv.w = s0p[(size_t)(r+3)*256];
#pragma unroll
            for (int j = 0; j < 16; j++) {
                float4 qv = *(const float4*)(qs + (pass*16+j)*KSTR + r);
                acc[j] += qv.x*sv.x + qv.y*sv.y + qv.z*sv.z + qv.w*sv.w;
            }
        }
#pragma unroll
        for (int j = 0; j < 16; j++) acc[j] *= ecl[pass*16+j];
#pragma unroll 1
        for (int i = 0; i < 64; i += 4) {
            float4 uvv;
            uvv.x = uas[(i+0)*256 + col];
            uvv.y = uas[(i+1)*256 + col];
            uvv.z = uas[(i+2)*256 + col];
            uvv.w = uas[(i+3)*256 + col];
#pragma unroll
            for (int j = 0; j < 16; j++) {
                float4 gv = *(const float4*)(Gq + (pass*16+j)*64 + i);
                acc[j] += gv.x*uvv.x + gv.y*uvv.y + gv.z*uvv.z + gv.w*uvv.w;
            }
        }
#pragma unroll
        for (int j = 0; j < 16; j++)
            o[(size_t)(row0 + pass*16+j)*VDq + h*DVq + col] = scale * acc[j];
    }
}

// ------------------------- gated RMSNorm -> bf16 hi/lo ----------------------
__global__ void rmsnorm_gate_kernel(const float* __restrict__ o,
                                    const float* __restrict__ P,
                                    const float* __restrict__ nw,
                                    __nv_bfloat16* __restrict__ oh,
                                    __nv_bfloat16* __restrict__ ol)
{
    int w = (blockIdx.x * blockDim.x + threadIdx.x) >> 5;
    int lane = threadIdx.x & 31;
    int row = w >> 3, hh = w & 7;
    const float* orow = o + (size_t)w * DVq;
    float4 o0 = *(const float4*)(orow + lane * 4);
    float4 o1 = *(const float4*)(orow + 128 + lane * 4);
    float ss = o0.x * o0.x + o0.y * o0.y + o0.z * o0.z + o0.w * o0.w
             + o1.x * o1.x + o1.y * o1.y + o1.z * o1.z + o1.w * o1.w;
#pragma unroll
    for (int m = 16; m; m >>= 1) ss += __shfl_xor_sync(0xffffffffu, ss, m);
    float r = rsqrtf(ss * (1.f / 256.f) + 1e-5f);
    const float* grow = P + (size_t)row * NFUSE + 4096 + hh * DVq;
    float4 g0 = *(const float4*)(grow + lane * 4);
    float4 g1 = *(const float4*)(grow + 128 + lane * 4);
    float4 w0 = *(const float4*)(nw + lane * 4);
    float4 w1 = *(const float4*)(nw + 128 + lane * 4);
    float f[8];
    f[0] = o0.x * r * w0.x * (g0.x / (1.f + expf(-g0.x)));
    f[1] = o0.y * r * w0.y * (g0.y / (1.f + expf(-g0.y)));
    f[2] = o0.z * r * w0.z * (g0.z / (1.f + expf(-g0.z)));
    f[3] = o0.w * r * w0.w * (g0.w / (1.f + expf(-g0.w)));
    f[4] = o1.x * r * w1.x * (g1.x / (1.f + expf(-g1.x)));
    f[5] = o1.y * r * w1.y * (g1.y / (1.f + expf(-g1.y)));
    f[6] = o1.z * r * w1.z * (g1.z / (1.f + expf(-g1.z)));
    f[7] = o1.w * r * w1.w * (g1.w / (1.f + expf(-g1.w)));
#pragma unroll
    for (int half = 0; half < 2; half++) {
        size_t base = (size_t)w * DVq + half * 128 + lane * 4;
        float a = f[half*4+0], b2 = f[half*4+1], c = f[half*4+2], d = f[half*4+3];
        split4(make_float4(a, b2, c, d), oh + base, ol + base);
    }
}

// ------------------------- launch -------------------------------------------
extern "C" void kernel_launch(void* const* d_in, const int* in_sizes, int n_in,
                              void* d_out, int out_size)
{
    const float* h        = (const float*)d_in[0];
    const float* q_w      = (const float*)d_in[1];
    const float* k_w      = (const float*)d_in[2];
    const float* v_w      = (const float*)d_in[3];
    const float* a_w      = (const float*)d_in[4];
    const float* b_w      = (const float*)d_in[5];
    const float* g_w      = (const float*)d_in[6];
    const float* o_w      = (const float*)d_in[7];
    const float* q_conv_w = (const float*)d_in[8];
    const float* k_conv_w = (const float*)d_in[9];
    const float* v_conv_w = (const float*)d_in[10];
    const float* A_log    = (const float*)d_in[11];
    const float* dt_bias  = (const float*)d_in[12];
    const float* o_norm_w = (const float*)d_in[13];
    float* out = (float*)d_out;

    float *P, *qc, *kc, *vc, *gd, *bt, *orow;
    float *cls, *uv, *wmp, *uap, *s0p;
    cudaGetSymbolAddress((void**)&P, g_proj);
    cudaGetSymbolAddress((void**)&qc, g_qc);
    cudaGetSymbolAddress((void**)&kc, g_kc);
    cudaGetSymbolAddress((void**)&vc, g_vc);
    cudaGetSymbolAddress((void**)&gd, g_gd);
    cudaGetSymbolAddress((void**)&bt, g_bt);
    cudaGetSymbolAddress((void**)&orow, g_orow);
    cudaGetSymbolAddress((void**)&cls, g_cls);
    cudaGetSymbolAddress((void**)&uv, g_uv);
    cudaGetSymbolAddress((void**)&wmp, g_wm);
    cudaGetSymbolAddress((void**)&uap, g_ua);
    cudaGetSymbolAddress((void**)&s0p, g_s0);

    __nv_bfloat16 *hh, *hl, *wh, *wl, *owh, *owl, *onh, *onl;
    cudaGetSymbolAddress((void**)&hh, g_hh);   cudaGetSymbolAddress((void**)&hl, g_hl);
    cudaGetSymbolAddress((void**)&wh, g_wh);   cudaGetSymbolAddress((void**)&wl, g_wl);
    cudaGetSymbolAddress((void**)&owh, g_owh); cudaGetSymbolAddress((void**)&owl, g_owl);
    cudaGetSymbolAddress((void**)&onh, g_onh); cudaGetSymbolAddress((void**)&onl, g_onl);

    cudaFuncSetAttribute(bgemm_nt_split, cudaFuncAttributeMaxDynamicSharedMemorySize, SMEM_GEMM);
    cudaFuncSetAttribute(chunk_solve_kernel, cudaFuncAttributeMaxDynamicSharedMemorySize, K1_SMEM);
    cudaFuncSetAttribute(chunk_state_kernel, cudaFuncAttributeMaxDynamicSharedMemorySize, K2_SMEM);
    cudaFuncSetAttribute(chunk_out_kernel,   cudaFuncAttributeMaxDynamicSharedMemorySize, K3_SMEM);

    // 0) bf16 hi/lo splits
    cvt_split<<<(Mrows*Dq/4 + 255)/256, 256>>>(h, hh, hl, Mrows*Dq);
    cvt_split_w4<<<(NFUSE*Dq/4 + 255)/256, 256>>>(q_w, k_w, v_w, g_w, wh, wl);
    cvt_split<<<(Dq*VDq/4 + 255)/256, 256>>>(o_w, owh, owl, Dq*VDq);

    // 1) fused q|k|v|gate projection on tensor cores
    bgemm_nt_split<<<dim3(NFUSE/128, Mrows/128), 256, SMEM_GEMM>>>(hh, hl, wh, wl, P, NFUSE);

    // 2) a/b projections -> decay + beta
    proj_ab_kernel<<<(Mrows * 32) / 256, 256>>>(h, a_w, b_w, A_log, dt_bias, gd, bt);

    // 3) conv+SiLU+l2norm for q,k ; conv+SiLU for v
    conv_l2_kernel<<<(Mrows * Hq * 32) / 256, 256>>>(P, 0,    q_conv_w, qc);
    conv_l2_kernel<<<(Mrows * Hq * 32) / 256, 256>>>(P, 1024, k_conv_w, kc);
    conv_silu_stride<<<(Mrows * VDq) / 256, 256>>>(P, 2048, v_conv_w, vc);

    // 4) chunked gated delta-rule scan
    chunk_solve_kernel<<<NU, 384, K1_SMEM>>>(kc, vc, gd, bt, uv, wmp, cls);
    chunk_state_kernel<<<dim3(16, Bq*Hq), 256, K2_SMEM>>>(kc, wmp, uv, cls, uap, s0p);
    chunk_out_kernel<<<NU, 256, K3_SMEM>>>(qc, kc, uap, s0p, cls, orow);

    // 5) gated RMSNorm (+ bf16 hi/lo split)
    rmsnorm_gate_kernel<<<(Mrows * Hq * 32) / 256, 256>>>(orow, P, o_norm_w, onh, onl);

    // 6) output projection -> d_out
    bgemm_nt_split<<<dim3(Dq/128, Mrows/128), 256, SMEM_GEMM>>>(onh, onl, owh, owl, out, Dq);
}

// round 11
// speedup vs baseline: 1.4236x; 1.1784x over previous
#include <cuda_runtime.h>
#include <cuda_bf16.h>
#include <math.h>
#include <stdint.h>

#define Bq 2
#define Tq 1024
#define Dq 2048
#define Hq 8
#define DKq 128
#define DVq 256
#define KDq 1024
#define VDq 2048
#define Mrows (Bq*Tq)   // 2048
#define GK 2048         // K for every big GEMM
#define NFUSE 6144      // q(1024) + k(1024) + v(2048) + gate(2048)

// ------------------------- scratch (device globals) -------------------------
__device__ float g_proj[Mrows*NFUSE];        // fused projection output
__device__ float g_qc[Mrows*KDq];
__device__ float g_kc[Mrows*KDq];
__device__ float g_vc[Mrows*VDq];
__device__ float g_gd[Mrows*Hq];
__device__ float g_bt[Mrows*Hq];
__device__ float g_orow[Mrows*VDq];

// bf16 split (hi/lo) operands
__device__ __nv_bfloat16 g_hh[Mrows*Dq],    g_hl[Mrows*Dq];
__device__ __nv_bfloat16 g_wh[NFUSE*Dq],    g_wl[NFUSE*Dq];    // fused q|k|v|g weights
__device__ __nv_bfloat16 g_owh[Dq*VDq],     g_owl[Dq*VDq];
__device__ __nv_bfloat16 g_onh[Mrows*VDq],  g_onl[Mrows*VDq];

// ------------------------- helpers ------------------------------------------
__device__ __forceinline__ uint32_t smem_u32(const void* p) {
    uint32_t a;
    asm("{ .reg .u64 t; cvta.to.shared.u64 t, %1; cvt.u32.u64 %0, t; }" : "=r"(a) : "l"(p));
    return a;
}
__device__ __forceinline__ void cp16(uint32_t dst, const void* src) {
    asm volatile("cp.async.cg.shared.global [%0], [%1], 16;" :: "r"(dst), "l"(src));
}
__device__ __forceinline__ void cp_commit() {
    asm volatile("cp.async.commit_group;" ::: "memory");
}
template <int N>
__device__ __forceinline__ void cp_wait() {
    asm volatile("cp.async.wait_group %0;" :: "n"(N) : "memory");
}
__device__ __forceinline__ void ldsm_x4(uint32_t addr, uint32_t* r) {
    asm volatile("ldmatrix.sync.aligned.m8n8.x4.shared.b16 {%0,%1,%2,%3}, [%4];"
                 : "=r"(r[0]), "=r"(r[1]), "=r"(r[2]), "=r"(r[3]) : "r"(addr));
}
__device__ __forceinline__ void mma_bf16(float* c, const uint32_t* a, const uint32_t* b) {
    asm volatile(
        "mma.sync.aligned.m16n8k16.row.col.f32.bf16.bf16.f32 "
        "{%0,%1,%2,%3}, {%4,%5,%6,%7}, {%8,%9}, {%0,%1,%2,%3};"
        : "+f"(c[0]), "+f"(c[1]), "+f"(c[2]), "+f"(c[3])
        : "r"(a[0]), "r"(a[1]), "r"(a[2]), "r"(a[3]), "r"(b[0]), "r"(b[1]));
}

// ------------------------- split bf16 HMMA GEMM (2-stage, 2 CTA/SM) ---------
#define ROWB 80
#define MATB (128*ROWB)
#define STGB (4*MATB)
#define SMEM_GEMM (2*STGB)

__global__ void __launch_bounds__(256, 2) bgemm_nt_split(
    const __nv_bfloat16* __restrict__ Ah, const __nv_bfloat16* __restrict__ Al,
    const __nv_bfloat16* __restrict__ Bh, const __nv_bfloat16* __restrict__ Bl,
    float* __restrict__ C, int N)
{
    extern __shared__ char smem[];
    const uint32_t sb = smem_u32(smem);
    const int tid = threadIdx.x, wid = tid >> 5, lane = tid & 31;
    const int bm = blockIdx.y * 128, bn = blockIdx.x * 128;
    const int wm = (wid >> 1) * 32;
    const int wn = (wid & 1) * 64;

    float acc[2][8][4];
#pragma unroll
    for (int i = 0; i < 2; i++)
#pragma unroll
        for (int j = 0; j < 8; j++)
#pragma unroll
            for (int l = 0; l < 4; l++) acc[i][j][l] = 0.f;

    const int NC = GK / 32;

#define PREFETCH(cc, ss)                                                          \
    {                                                                             \
        const int kc = (cc) * 32;                                                 \
        const uint32_t stg = sb + (uint32_t)(ss) * STGB;                          \
        _Pragma("unroll")                                                         \
        for (int i = 0; i < 2; i++) {                                             \
            int idx = tid + i * 256;                                              \
            int row = idx >> 2, seg = idx & 3;                                    \
            uint32_t so = (uint32_t)(row * ROWB + seg * 16);                      \
            size_t ea = (size_t)(bm + row) * GK + kc + seg * 8;                   \
            size_t eb = (size_t)(bn + row) * GK + kc + seg * 8;                   \
            cp16(stg + so,            Ah + ea);                                   \
            cp16(stg + MATB + so,     Al + ea);                                   \
            cp16(stg + 2*MATB + so,   Bh + eb);                                   \
            cp16(stg + 3*MATB + so,   Bl + eb);                                   \
        }                                                                         \
        cp_commit();                                                              \
    }

    PREFETCH(0, 0);
    PREFETCH(1, 1);

    const uint32_t a_row = (uint32_t)(wm + (lane & 15));
    const uint32_t a_colb = (uint32_t)((lane >> 4) * 16);
    const uint32_t b_row0 = (uint32_t)(wn + (lane & 7) + ((lane >> 4) << 3));
    const uint32_t b_colb = (uint32_t)(((lane >> 3) & 1) * 16);

    for (int c = 0; c < NC; c++) {
        if (c == NC - 1) cp_wait<0>(); else cp_wait<1>();
        __syncthreads();
        const uint32_t stg = sb + (uint32_t)(c & 1) * STGB;

#pragma unroll
        for (int k16 = 0; k16 < 2; k16++) {
            const uint32_t kb = (uint32_t)(k16 * 32);
            uint32_t a0[2][4], a1[2][4], bb[4][4];

#pragma unroll
            for (int mt = 0; mt < 2; mt++) {
                uint32_t ao = (a_row + mt * 16) * ROWB + kb + a_colb;
                ldsm_x4(stg + ao, a0[mt]);
            }
#pragma unroll
            for (int np = 0; np < 4; np++) {
                uint32_t bo = (b_row0 + np * 16) * ROWB + kb + b_colb;
                ldsm_x4(stg + 2*MATB + bo, bb[np]);
            }
#pragma unroll
            for (int mt = 0; mt < 2; mt++)
#pragma unroll
                for (int np = 0; np < 4; np++) {
                    mma_bf16(acc[mt][np*2],   a0[mt], bb[np]);
                    mma_bf16(acc[mt][np*2+1], a0[mt], bb[np] + 2);
                }

#pragma unroll
            for (int mt = 0; mt < 2; mt++) {
                uint32_t ao = (a_row + mt * 16) * ROWB + kb + a_colb;
                ldsm_x4(stg + MATB + ao, a1[mt]);
            }
#pragma unroll
            for (int mt = 0; mt < 2; mt++)
#pragma unroll
                for (int np = 0; np < 4; np++) {
                    mma_bf16(acc[mt][np*2],   a1[mt], bb[np]);
                    mma_bf16(acc[mt][np*2+1], a1[mt], bb[np] + 2);
                }

#pragma unroll
            for (int np = 0; np < 4; np++) {
                uint32_t bo = (b_row0 + np * 16) * ROWB + kb + b_colb;
                ldsm_x4(stg + 3*MATB + bo, bb[np]);
            }
#pragma unroll
            for (int mt = 0; mt < 2; mt++)
#pragma unroll
                for (int np = 0; np < 4; np++) {
                    mma_bf16(acc[mt][np*2],   a0[mt], bb[np]);
                    mma_bf16(acc[mt][np*2+1], a0[mt], bb[np] + 2);
                }
        }
        __syncthreads();
        if (c + 2 < NC) PREFETCH(c + 2, c & 1);
    }
#undef PREFETCH

#pragma unroll
    for (int mt = 0; mt < 2; mt++) {
        int r0 = bm + wm + mt * 16 + (lane >> 2);
#pragma unroll
        for (int nt = 0; nt < 8; nt++) {
            int col = bn + wn + nt * 8 + (lane & 3) * 2;
            float2 v0 = make_float2(acc[mt][nt][0], acc[mt][nt][1]);
            float2 v1 = make_float2(acc[mt][nt][2], acc[mt][nt][3]);
            *(float2*)(C + (size_t)r0 * N + col)       = v0;
            *(float2*)(C + (size_t)(r0 + 8) * N + col) = v1;
        }
    }
}

// ------------------------- fp32 -> bf16 hi/lo split -------------------------
__device__ __forceinline__ void split4(float4 v, __nv_bfloat16* hi, __nv_bfloat16* lo) {
    __nv_bfloat16 hx = __float2bfloat16(v.x), hy = __float2bfloat16(v.y);
    __nv_bfloat16 hz = __float2bfloat16(v.z), hw = __float2bfloat16(v.w);
    __nv_bfloat162 h0, h1, l0, l1;
    h0.x = hx; h0.y = hy; h1.x = hz; h1.y = hw;
    l0.x = __float2bfloat16(v.x - __bfloat162float(hx));
    l0.y = __float2bfloat16(v.y - __bfloat162float(hy));
    l1.x = __float2bfloat16(v.z - __bfloat162float(hz));
    l1.y = __float2bfloat16(v.w - __bfloat162float(hw));
    *(__nv_bfloat162*)(hi)     = h0;
    *(__nv_bfloat162*)(hi + 2) = h1;
    *(__nv_bfloat162*)(lo)     = l0;
    *(__nv_bfloat162*)(lo + 2) = l1;
}

__global__ void cvt_split(const float* __restrict__ x,
                          __nv_bfloat16* __restrict__ hi,
                          __nv_bfloat16* __restrict__ lo, int n)
{
    int i = (blockIdx.x * blockDim.x + threadIdx.x) * 4;
    if (i >= n) return;
    split4(*(const float4*)(x + i), hi + i, lo + i);
}

__global__ void cvt_split_w4(const float* __restrict__ qw, const float* __restrict__ kw,
                             const float* __restrict__ vw, const float* __restrict__ gw,
                             __nv_bfloat16* __restrict__ hi, __nv_bfloat16* __restrict__ lo)
{
    int i = (blockIdx.x * blockDim.x + threadIdx.x) * 4;
    int row = i >> 11;
    int col = i & 2047;
    const float* src;
    if (row < 1024)      src = qw + (size_t)row * Dq + col;
    else if (row < 2048) src = kw + (size_t)(row - 1024) * Dq + col;
    else if (row < 4096) src = vw + (size_t)(row - 2048) * Dq + col;
    else                 src = gw + (size_t)(row - 4096) * Dq + col;
    split4(*(const float4*)src, hi + i, lo + i);
}

// ------------------------- a/b projections -> decay g and beta --------------
__device__ __forceinline__ float softplus_f(float x) {
    return fmaxf(x, 0.f) + log1pf(expf(-fabsf(x)));
}

__global__ void proj_ab_kernel(const float* __restrict__ h,
                               const float* __restrict__ a_w,
                               const float* __restrict__ b_w,
                               const float* __restrict__ A_log,
                               const float* __restrict__ dt_bias,
                               float* __restrict__ gd, float* __restrict__ bt)
{
    int w = (blockIdx.x * blockDim.x + threadIdx.x) >> 5;
    int lane = threadIdx.x & 31;
    if (w >= Mrows) return;
    const float* hr = h + (size_t)w * Dq;
    float acc[16];
#pragma unroll
    for (int p = 0; p < 16; p++) acc[p] = 0.f;
    for (int j = lane * 4; j < Dq; j += 128) {
        float4 hv = *(const float4*)(hr + j);
#pragma unroll
        for (int p = 0; p < 8; p++) {
            float4 av = *(const float4*)(a_w + (size_t)p * Dq + j);
            acc[p] += hv.x * av.x + hv.y * av.y + hv.z * av.z + hv.w * av.w;
            float4 bv = *(const float4*)(b_w + (size_t)p * Dq + j);
            acc[8 + p] += hv.x * bv.x + hv.y * bv.y + hv.z * bv.z + hv.w * bv.w;
        }
    }
#pragma unroll
    for (int p = 0; p < 16; p++)
#pragma unroll
        for (int m = 16; m; m >>= 1)
            acc[p] += __shfl_xor_sync(0xffffffffu, acc[p], m);

    if (lane < 8) {
        float x = acc[lane] + dt_bias[lane];
        gd[w * Hq + lane] = -expf(A_log[lane]) * softplus_f(x);
    } else if (lane < 16) {
        int p = lane - 8;
        bt[w * Hq + p] = 1.f / (1.f + expf(-acc[lane]));
    }
}

// ---------------- fused conv+SiLU+l2norm for q/k (head dim 128) -------------
__global__ void conv_l2_kernel(const float* __restrict__ P, int colofs,
                               const float* __restrict__ w, float* __restrict__ out)
{
    int gwp = (blockIdx.x * blockDim.x + threadIdx.x) >> 5;
    int lane = threadIdx.x & 31;
    int row = gwp >> 3, hh = gwp & 7;
    int t = row & (Tq - 1);
    int c = hh * 128 + lane * 4;
    const float* base = P + (size_t)row * NFUSE + colofs + c;
    float4 x0 = *(const float4*)base;
    float4 x1 = make_float4(0,0,0,0), x2 = x1, x3 = x1;
    if (t >= 1) x1 = *(const float4*)(base - NFUSE);
    if (t >= 2) x2 = *(const float4*)(base - 2*NFUSE);
    if (t >= 3) x3 = *(const float4*)(base - 3*NFUSE);
    float4 wc0 = *(const float4*)(w + (size_t)(c + 0) * 4);
    float4 wc1 = *(const float4*)(w + (size_t)(c + 1) * 4);
    float4 wc2 = *(const float4*)(w + (size_t)(c + 2) * 4);
    float4 wc3 = *(const float4*)(w + (size_t)(c + 3) * 4);
    float v0 = x0.x*wc0.w + x1.x*wc0.z + x2.x*wc0.y + x3.x*wc0.x;
    float v1 = x0.y*wc1.w + x1.y*wc1.z + x2.y*wc1.y + x3.y*wc1.x;
    float v2 = x0.z*wc2.w + x1.z*wc2.z + x2.z*wc2.y + x3.z*wc2.x;
    float v3 = x0.w*wc3.w + x1.w*wc3.z + x2.w*wc3.y + x3.w*wc3.x;
    v0 = v0 / (1.f + expf(-v0));
    v1 = v1 / (1.f + expf(-v1));
    v2 = v2 / (1.f + expf(-v2));
    v3 = v3 / (1.f + expf(-v3));
    float ss = v0*v0 + v1*v1 + v2*v2 + v3*v3;
#pragma unroll
    for (int m = 16; m; m >>= 1) ss += __shfl_xor_sync(0xffffffffu, ss, m);
    float r = rsqrtf(ss + 1e-6f);
    *(float4*)(out + (size_t)row * KDq + c) =
        make_float4(v0 * r, v1 * r, v2 * r, v3 * r);
}

// ---------------- conv+SiLU for v (elementwise, strided read) ---------------
__global__ void conv_silu_stride(const float* __restrict__ P, int colofs,
                                 const float* __restrict__ w, float* __restrict__ out)
{
    int i = blockIdx.x * blockDim.x + threadIdx.x;
    int c = i % VDq;
    int row = i / VDq;
    int t = row & (Tq - 1);
    const float* base = P + (size_t)row * NFUSE + colofs + c;
    float4 wc = *(const float4*)(w + (size_t)c * 4);
    float acc = base[0] * wc.w;
    if (t >= 1) acc += base[-1 * NFUSE] * wc.z;
    if (t >= 2) acc += base[-2 * NFUSE] * wc.y;
    if (t >= 3) acc += base[-3 * NFUSE] * wc.x;
    out[i] = acc / (1.f + expf(-acc));
}

// ------------------------- gated delta-rule scan (16-col chunks) ------------
// grid (DV/16=16, H, B) = 256 CTAs, 128 threads. col = tid>>3 (16 cols),
// rgrp = tid&7 owns 16 k-rows (S[16] regs). 3-level shfl reductions.
// k/q tile layout: per step, 8 groups of 16 floats at stride 20 words
// (rgrp*20 mod 32 covers all banks exactly once -> conflict-free LDS.128).
#define TS 16
#define GSTR 160
__global__ void __launch_bounds__(128) scan_kernel(const float* __restrict__ q,
                                                   const float* __restrict__ k,
                                                   const float* __restrict__ v,
                                                   const float* __restrict__ gdec,
                                                   const float* __restrict__ beta,
                                                   float* __restrict__ o)
{
    const int vchunk = blockIdx.x;     // 0..15
    const int h = blockIdx.y;
    const int b = blockIdx.z;
    const int tid = threadIdx.x;
    const int col = tid >> 3;          // 0..15
    const int rgrp = tid & 7;          // 8 groups x 16 rows
    const int c0 = vchunk * 16;

    __shared__ float ks[TS * GSTR];
    __shared__ float qs[TS * GSTR];
    __shared__ float vs[TS * 16];
    __shared__ float egs[TS];
    __shared__ float bss[TS];

    float S[16];
#pragma unroll
    for (int i = 0; i < 16; i++) S[i] = 0.f;
    const float scale = 0.08838834764831843f;

    for (int t0 = 0; t0 < Tq; t0 += TS) {
        __syncthreads();
#pragma unroll
        for (int j = 0; j < 4; j++) {
            int idx = tid + j * 128;           // 0..511
            int s = idx >> 5, f = idx & 31;    // step, float4 index
            size_t gofs = ((size_t)(b * Tq + t0 + s)) * KDq + h * DKq + f * 4;
            int so = s * GSTR + (f >> 2) * 20 + (f & 3) * 4;
            *(float4*)(ks + so) = *(const float4*)(k + gofs);
            *(float4*)(qs + so) = *(const float4*)(q + gofs);
        }
        if (tid < 64) {
            int s = tid >> 2, f = tid & 3;
            size_t gofs = ((size_t)(b * Tq + t0 + s)) * VDq + h * DVq + c0 + f * 4;
            *(float4*)(vs + s * 16 + f * 4) = *(const float4*)(v + gofs);
        }
        if (tid < TS) egs[tid] = expf(gdec[(size_t)(b * Tq + t0 + tid) * Hq + h]);
        else if (tid < 2 * TS) bss[tid - TS] = beta[(size_t)(b * Tq + t0 + tid - TS) * Hq + h];
        __syncthreads();

#pragma unroll
        for (int s = 0; s < TS; s++) {
            const float* kb = ks + s * GSTR + rgrp * 20;
            const float* qb = qs + s * GSTR + rgrp * 20;
            float4 k0 = *(const float4*)(kb);
            float4 k1 = *(const float4*)(kb + 4);
            float4 k2 = *(const float4*)(kb + 8);
            float4 k3 = *(const float4*)(kb + 12);
            float kva = k0.x*S[0] + k0.y*S[1] + k0.z*S[2] + k0.w*S[3];
            float kvb = k1.x*S[4] + k1.y*S[5] + k1.z*S[6] + k1.w*S[7];
            float kvc = k2.x*S[8] + k2.y*S[9] + k2.z*S[10] + k2.w*S[11];
            float kvd = k3.x*S[12] + k3.y*S[13] + k3.z*S[14] + k3.w*S[15];
            float kv = (kva + kvb) + (kvc + kvd);
            kv += __shfl_xor_sync(0xffffffffu, kv, 1);
            kv += __shfl_xor_sync(0xffffffffu, kv, 2);
            kv += __shfl_xor_sync(0xffffffffu, kv, 4);
            float eg = egs[s];
            float u = (vs[s * 16 + col] - kv * eg) * bss[s];
            float4 q0 = *(const float4*)(qb);
            float4 q1 = *(const float4*)(qb + 4);
            float4 q2 = *(const float4*)(qb + 8);
            float4 q3 = *(const float4*)(qb + 12);
            S[0]  = S[0]*eg  + k0.x*u;  S[1]  = S[1]*eg  + k0.y*u;
            S[2]  = S[2]*eg  + k0.z*u;  S[3]  = S[3]*eg  + k0.w*u;
            S[4]  = S[4]*eg  + k1.x*u;  S[5]  = S[5]*eg  + k1.y*u;
            S[6]  = S[6]*eg  + k1.z*u;  S[7]  = S[7]*eg  + k1.w*u;
            S[8]  = S[8]*eg  + k2.x*u;  S[9]  = S[9]*eg  + k2.y*u;
            S[10] = S[10]*eg + k2.z*u;  S[11] = S[11]*eg + k2.w*u;
            S[12] = S[12]*eg + k3.x*u;  S[13] = S[13]*eg + k3.y*u;
            S[14] = S[14]*eg + k3.z*u;  S[15] = S[15]*eg + k3.w*u;
            float oa = q0.x*S[0] + q0.y*S[1] + q0.z*S[2] + q0.w*S[3];
            float ob = q1.x*S[4] + q1.y*S[5] + q1.z*S[6] + q1.w*S[7];
            float oc = q2.x*S[8] + q2.y*S[9] + q2.z*S[10] + q2.w*S[11];
            float od = q3.x*S[12] + q3.y*S[13] + q3.z*S[14] + q3.w*S[15];
            float ot = (oa + ob) + (oc + od);
            ot += __shfl_xor_sync(0xffffffffu, ot, 1);
            ot += __shfl_xor_sync(0xffffffffu, ot, 2);
            ot += __shfl_xor_sync(0xffffffffu, ot, 4);
            if (rgrp == 0)
                o[(size_t)(b * Tq + t0 + s) * VDq + h * DVq + c0 + col] = ot * scale;
        }
    }
}

// ------------------------- gated RMSNorm -> bf16 hi/lo ----------------------
__global__ void rmsnorm_gate_kernel(const float* __restrict__ o,
                                    const float* __restrict__ P,   // gate at col 4096
                                    const float* __restrict__ nw,
                                    __nv_bfloat16* __restrict__ oh,
                                    __nv_bfloat16* __restrict__ ol)
{
    int w = (blockIdx.x * blockDim.x + threadIdx.x) >> 5;   // (b,t,h) id
    int lane = threadIdx.x & 31;
    int row = w >> 3, hh = w & 7;
    const float* orow = o + (size_t)w * DVq;
    float4 o0 = *(const float4*)(orow + lane * 4);
    float4 o1 = *(const float4*)(orow + 128 + lane * 4);
    float ss = o0.x * o0.x + o0.y * o0.y + o0.z * o0.z + o0.w * o0.w
             + o1.x * o1.x + o1.y * o1.y + o1.z * o1.z + o1.w * o1.w;
#pragma unroll
    for (int m = 16; m; m >>= 1) ss += __shfl_xor_sync(0xffffffffu, ss, m);
    float r = rsqrtf(ss * (1.f / 256.f) + 1e-5f);
    const float* grow = P + (size_t)row * NFUSE + 4096 + hh * DVq;
    float4 g0 = *(const float4*)(grow + lane * 4);
    float4 g1 = *(const float4*)(grow + 128 + lane * 4);
    float4 w0 = *(const float4*)(nw + lane * 4);
    float4 w1 = *(const float4*)(nw + 128 + lane * 4);
    float f[8];
    f[0] = o0.x * r * w0.x * (g0.x / (1.f + expf(-g0.x)));
    f[1] = o0.y * r * w0.y * (g0.y / (1.f + expf(-g0.y)));
    f[2] = o0.z * r * w0.z * (g0.z / (1.f + expf(-g0.z)));
    f[3] = o0.w * r * w0.w * (g0.w / (1.f + expf(-g0.w)));
    f[4] = o1.x * r * w1.x * (g1.x / (1.f + expf(-g1.x)));
    f[5] = o1.y * r * w1.y * (g1.y / (1.f + expf(-g1.y)));
    f[6] = o1.z * r * w1.z * (g1.z / (1.f + expf(-g1.z)));
    f[7] = o1.w * r * w1.w * (g1.w / (1.f + expf(-g1.w)));
#pragma unroll
    for (int half = 0; half < 2; half++) {
        size_t base = (size_t)w * DVq + half * 128 + lane * 4;
        float a = f[half*4+0], b2 = f[half*4+1], c = f[half*4+2], d = f[half*4+3];
        split4(make_float4(a, b2, c, d), oh + base, ol + base);
    }
}

// ------------------------- launch -------------------------------------------
extern "C" void kernel_launch(void* const* d_in, const int* in_sizes, int n_in,
                              void* d_out, int out_size)
{
    const float* h        = (const float*)d_in[0];
    const float* q_w      = (const float*)d_in[1];
    const float* k_w      = (const float*)d_in[2];
    const float* v_w      = (const float*)d_in[3];
    const float* a_w      = (const float*)d_in[4];
    const float* b_w      = (const float*)d_in[5];
    const float* g_w      = (const float*)d_in[6];
    const float* o_w      = (const float*)d_in[7];
    const float* q_conv_w = (const float*)d_in[8];
    const float* k_conv_w = (const float*)d_in[9];
    const float* v_conv_w = (const float*)d_in[10];
    const float* A_log    = (const float*)d_in[11];
    const float* dt_bias  = (const float*)d_in[12];
    const float* o_norm_w = (const float*)d_in[13];
    float* out = (float*)d_out;

    float *P, *qc, *kc, *vc, *gd, *bt, *orow;
    cudaGetSymbolAddress((void**)&P, g_proj);
    cudaGetSymbolAddress((void**)&qc, g_qc);
    cudaGetSymbolAddress((void**)&kc, g_kc);
    cudaGetSymbolAddress((void**)&vc, g_vc);
    cudaGetSymbolAddress((void**)&gd, g_gd);
    cudaGetSymbolAddress((void**)&bt, g_bt);
    cudaGetSymbolAddress((void**)&orow, g_orow);

    __nv_bfloat16 *hh, *hl, *wh, *wl, *owh, *owl, *onh, *onl;
    cudaGetSymbolAddress((void**)&hh, g_hh);   cudaGetSymbolAddress((void**)&hl, g_hl);
    cudaGetSymbolAddress((void**)&wh, g_wh);   cudaGetSymbolAddress((void**)&wl, g_wl);
    cudaGetSymbolAddress((void**)&owh, g_owh); cudaGetSymbolAddress((void**)&owl, g_owl);
    cudaGetSymbolAddress((void**)&onh, g_onh); cudaGetSymbolAddress((void**)&onl, g_onl);

    cudaFuncSetAttribute(bgemm_nt_split, cudaFuncAttributeMaxDynamicSharedMemorySize, SMEM_GEMM);

    // 0) bf16 hi/lo splits
    cvt_split<<<(Mrows*Dq/4 + 255)/256, 256>>>(h, hh, hl, Mrows*Dq);
    cvt_split_w4<<<(NFUSE*Dq/4 + 255)/256, 256>>>(q_w, k_w, v_w, g_w, wh, wl);
    cvt_split<<<(Dq*VDq/4 + 255)/256, 256>>>(o_w, owh, owl, Dq*VDq);

    // 1) fused q|k|v|gate projection on tensor cores
    bgemm_nt_split<<<dim3(NFUSE/128, Mrows/128), 256, SMEM_GEMM>>>(hh, hl, wh, wl, P, NFUSE);

    // 2) a/b projections -> decay + beta
    proj_ab_kernel<<<(Mrows * 32) / 256, 256>>>(h, a_w, b_w, A_log, dt_bias, gd, bt);

    // 3) conv+SiLU+l2norm for q,k ; conv+SiLU for v
    conv_l2_kernel<<<(Mrows * Hq * 32) / 256, 256>>>(P, 0,    q_conv_w, qc);
    conv_l2_kernel<<<(Mrows * Hq * 32) / 256, 256>>>(P, 1024, k_conv_w, kc);
    conv_silu_stride<<<(Mrows * VDq) / 256, 256>>>(P, 2048, v_conv_w, vc);

    // 4) gated delta-rule recurrence (16-col chunks, 256 CTAs)
    scan_kernel<<<dim3(DVq / 16, Hq, Bq), 128>>>(qc, kc, vc, gd, bt, orow);

    // 5) gated RMSNorm (+ bf16 hi/lo split)
    rmsnorm_gate_kernel<<<(Mrows * Hq * 32) / 256, 256>>>(orow, P, o_norm_w, onh, onl);

    // 6) output projection -> d_out
    bgemm_nt_split<<<dim3(Dq/128, Mrows/128), 256, SMEM_GEMM>>>(onh, onl, owh, owl, out, Dq);
}

// round 12
// speedup vs baseline: 1.4539x; 1.0213x over previous
#include <cuda_runtime.h>
#include <cuda_bf16.h>
#include <math.h>
#include <stdint.h>

#define Bq 2
#define Tq 1024
#define Dq 2048
#define Hq 8
#define DKq 128
#define DVq 256
#define KDq 1024
#define VDq 2048
#define Mrows (Bq*Tq)   // 2048
#define GK 2048         // K for every big GEMM
#define NFUSE 6144      // q(1024) + k(1024) + v(2048) + gate(2048)

// ------------------------- scratch (device globals) -------------------------
__device__ float g_proj[Mrows*NFUSE];        // fused projection output
__device__ float g_qc[Mrows*KDq];
__device__ float g_kc[Mrows*KDq];
__device__ float g_vc[Mrows*VDq];
__device__ float g_gd[Mrows*Hq];
__device__ float g_bt[Mrows*Hq];
__device__ float g_orow[Mrows*VDq];

// bf16 split (hi/lo) operands
__device__ __nv_bfloat16 g_hh[Mrows*Dq],    g_hl[Mrows*Dq];
__device__ __nv_bfloat16 g_wh[NFUSE*Dq],    g_wl[NFUSE*Dq];    // fused q|k|v|g weights
__device__ __nv_bfloat16 g_owh[Dq*VDq],     g_owl[Dq*VDq];
__device__ __nv_bfloat16 g_onh[Mrows*VDq],  g_onl[Mrows*VDq];

// ------------------------- helpers ------------------------------------------
__device__ __forceinline__ uint32_t smem_u32(const void* p) {
    uint32_t a;
    asm("{ .reg .u64 t; cvta.to.shared.u64 t, %1; cvt.u32.u64 %0, t; }" : "=r"(a) : "l"(p));
    return a;
}
__device__ __forceinline__ void cp16(uint32_t dst, const void* src) {
    asm volatile("cp.async.cg.shared.global [%0], [%1], 16;" :: "r"(dst), "l"(src));
}
__device__ __forceinline__ void cp4(uint32_t dst, const void* src) {
    asm volatile("cp.async.ca.shared.global [%0], [%1], 4;" :: "r"(dst), "l"(src));
}
__device__ __forceinline__ void cp_commit() {
    asm volatile("cp.async.commit_group;" ::: "memory");
}
template <int N>
__device__ __forceinline__ void cp_wait() {
    asm volatile("cp.async.wait_group %0;" :: "n"(N) : "memory");
}
__device__ __forceinline__ void ldsm_x4(uint32_t addr, uint32_t* r) {
    asm volatile("ldmatrix.sync.aligned.m8n8.x4.shared.b16 {%0,%1,%2,%3}, [%4];"
                 : "=r"(r[0]), "=r"(r[1]), "=r"(r[2]), "=r"(r[3]) : "r"(addr));
}
__device__ __forceinline__ void mma_bf16(float* c, const uint32_t* a, const uint32_t* b) {
    asm volatile(
        "mma.sync.aligned.m16n8k16.row.col.f32.bf16.bf16.f32 "
        "{%0,%1,%2,%3}, {%4,%5,%6,%7}, {%8,%9}, {%0,%1,%2,%3};"
        : "+f"(c[0]), "+f"(c[1]), "+f"(c[2]), "+f"(c[3])
        : "r"(a[0]), "r"(a[1]), "r"(a[2]), "r"(a[3]), "r"(b[0]), "r"(b[1]));
}

// ------------------------- split bf16 HMMA GEMM (2-stage, 2 CTA/SM) ---------
#define ROWB 80
#define MATB (128*ROWB)
#define STGB (4*MATB)
#define SMEM_GEMM (2*STGB)

__global__ void __launch_bounds__(256, 2) bgemm_nt_split(
    const __nv_bfloat16* __restrict__ Ah, const __nv_bfloat16* __restrict__ Al,
    const __nv_bfloat16* __restrict__ Bh, const __nv_bfloat16* __restrict__ Bl,
    float* __restrict__ C, int N)
{
    extern __shared__ char smem[];
    const uint32_t sb = smem_u32(smem);
    const int tid = threadIdx.x, wid = tid >> 5, lane = tid & 31;
    const int bm = blockIdx.y * 128, bn = blockIdx.x * 128;
    const int wm = (wid >> 1) * 32;
    const int wn = (wid & 1) * 64;

    float acc[2][8][4];
#pragma unroll
    for (int i = 0; i < 2; i++)
#pragma unroll
        for (int j = 0; j < 8; j++)
#pragma unroll
            for (int l = 0; l < 4; l++) acc[i][j][l] = 0.f;

    const int NC = GK / 32;

#define PREFETCH(cc, ss)                                                          \
    {                                                                             \
        const int kc = (cc) * 32;                                                 \
        const uint32_t stg = sb + (uint32_t)(ss) * STGB;                          \
        _Pragma("unroll")                                                         \
        for (int i = 0; i < 2; i++) {                                             \
            int idx = tid + i * 256;                                              \
            int row = idx >> 2, seg = idx & 3;                                    \
            uint32_t so = (uint32_t)(row * ROWB + seg * 16);                      \
            size_t ea = (size_t)(bm + row) * GK + kc + seg * 8;                   \
            size_t eb = (size_t)(bn + row) * GK + kc + seg * 8;                   \
            cp16(stg + so,            Ah + ea);                                   \
            cp16(stg + MATB + so,     Al + ea);                                   \
            cp16(stg + 2*MATB + so,   Bh + eb);                                   \
            cp16(stg + 3*MATB + so,   Bl + eb);                                   \
        }                                                                         \
        cp_commit();                                                              \
    }

    PREFETCH(0, 0);
    PREFETCH(1, 1);

    const uint32_t a_row = (uint32_t)(wm + (lane & 15));
    const uint32_t a_colb = (uint32_t)((lane >> 4) * 16);
    const uint32_t b_row0 = (uint32_t)(wn + (lane & 7) + ((lane >> 4) << 3));
    const uint32_t b_colb = (uint32_t)(((lane >> 3) & 1) * 16);

    for (int c = 0; c < NC; c++) {
        if (c == NC - 1) cp_wait<0>(); else cp_wait<1>();
        __syncthreads();
        const uint32_t stg = sb + (uint32_t)(c & 1) * STGB;

#pragma unroll
        for (int k16 = 0; k16 < 2; k16++) {
            const uint32_t kb = (uint32_t)(k16 * 32);
            uint32_t a0[2][4], a1[2][4], bb[4][4];

#pragma unroll
            for (int mt = 0; mt < 2; mt++) {
                uint32_t ao = (a_row + mt * 16) * ROWB + kb + a_colb;
                ldsm_x4(stg + ao, a0[mt]);
            }
#pragma unroll
            for (int np = 0; np < 4; np++) {
                uint32_t bo = (b_row0 + np * 16) * ROWB + kb + b_colb;
                ldsm_x4(stg + 2*MATB + bo, bb[np]);
            }
#pragma unroll
            for (int mt = 0; mt < 2; mt++)
#pragma unroll
                for (int np = 0; np < 4; np++) {
                    mma_bf16(acc[mt][np*2],   a0[mt], bb[np]);
                    mma_bf16(acc[mt][np*2+1], a0[mt], bb[np] + 2);
                }

#pragma unroll
            for (int mt = 0; mt < 2; mt++) {
                uint32_t ao = (a_row + mt * 16) * ROWB + kb + a_colb;
                ldsm_x4(stg + MATB + ao, a1[mt]);
            }
#pragma unroll
            for (int mt = 0; mt < 2; mt++)
#pragma unroll
                for (int np = 0; np < 4; np++) {
                    mma_bf16(acc[mt][np*2],   a1[mt], bb[np]);
                    mma_bf16(acc[mt][np*2+1], a1[mt], bb[np] + 2);
                }

#pragma unroll
            for (int np = 0; np < 4; np++) {
                uint32_t bo = (b_row0 + np * 16) * ROWB + kb + b_colb;
                ldsm_x4(stg + 3*MATB + bo, bb[np]);
            }
#pragma unroll
            for (int mt = 0; mt < 2; mt++)
#pragma unroll
                for (int np = 0; np < 4; np++) {
                    mma_bf16(acc[mt][np*2],   a0[mt], bb[np]);
                    mma_bf16(acc[mt][np*2+1], a0[mt], bb[np] + 2);
                }
        }
        __syncthreads();
        if (c + 2 < NC) PREFETCH(c + 2, c & 1);
    }
#undef PREFETCH

#pragma unroll
    for (int mt = 0; mt < 2; mt++) {
        int r0 = bm + wm + mt * 16 + (lane >> 2);
#pragma unroll
        for (int nt = 0; nt < 8; nt++) {
            int col = bn + wn + nt * 8 + (lane & 3) * 2;
            float2 v0 = make_float2(acc[mt][nt][0], acc[mt][nt][1]);
            float2 v1 = make_float2(acc[mt][nt][2], acc[mt][nt][3]);
            *(float2*)(C + (size_t)r0 * N + col)       = v0;
            *(float2*)(C + (size_t)(r0 + 8) * N + col) = v1;
        }
    }
}

// ------------------------- fp32 -> bf16 hi/lo split -------------------------
__device__ __forceinline__ void split4(float4 v, __nv_bfloat16* hi, __nv_bfloat16* lo) {
    __nv_bfloat16 hx = __float2bfloat16(v.x), hy = __float2bfloat16(v.y);
    __nv_bfloat16 hz = __float2bfloat16(v.z), hw = __float2bfloat16(v.w);
    __nv_bfloat162 h0, h1, l0, l1;
    h0.x = hx; h0.y = hy; h1.x = hz; h1.y = hw;
    l0.x = __float2bfloat16(v.x - __bfloat162float(hx));
    l0.y = __float2bfloat16(v.y - __bfloat162float(hy));
    l1.x = __float2bfloat16(v.z - __bfloat162float(hz));
    l1.y = __float2bfloat16(v.w - __bfloat162float(hw));
    *(__nv_bfloat162*)(hi)     = h0;
    *(__nv_bfloat162*)(hi + 2) = h1;
    *(__nv_bfloat162*)(lo)     = l0;
    *(__nv_bfloat162*)(lo + 2) = l1;
}

__global__ void cvt_split(const float* __restrict__ x,
                          __nv_bfloat16* __restrict__ hi,
                          __nv_bfloat16* __restrict__ lo, int n)
{
    int i = (blockIdx.x * blockDim.x + threadIdx.x) * 4;
    if (i >= n) return;
    split4(*(const float4*)(x + i), hi + i, lo + i);
}

__global__ void cvt_split_w4(const float* __restrict__ qw, const float* __restrict__ kw,
                             const float* __restrict__ vw, const float* __restrict__ gw,
                             __nv_bfloat16* __restrict__ hi, __nv_bfloat16* __restrict__ lo)
{
    int i = (blockIdx.x * blockDim.x + threadIdx.x) * 4;
    int row = i >> 11;
    int col = i & 2047;
    const float* src;
    if (row < 1024)      src = qw + (size_t)row * Dq + col;
    else if (row < 2048) src = kw + (size_t)(row - 1024) * Dq + col;
    else if (row < 4096) src = vw + (size_t)(row - 2048) * Dq + col;
    else                 src = gw + (size_t)(row - 4096) * Dq + col;
    split4(*(const float4*)src, hi + i, lo + i);
}

// ------------------------- a/b projections -> decay g and beta --------------
__device__ __forceinline__ float softplus_f(float x) {
    return fmaxf(x, 0.f) + log1pf(expf(-fabsf(x)));
}

__global__ void proj_ab_kernel(const float* __restrict__ h,
                               const float* __restrict__ a_w,
                               const float* __restrict__ b_w,
                               const float* __restrict__ A_log,
                               const float* __restrict__ dt_bias,
                               float* __restrict__ gd, float* __restrict__ bt)
{
    int w = (blockIdx.x * blockDim.x + threadIdx.x) >> 5;
    int lane = threadIdx.x & 31;
    if (w >= Mrows) return;
    const float* hr = h + (size_t)w * Dq;
    float acc[16];
#pragma unroll
    for (int p = 0; p < 16; p++) acc[p] = 0.f;
    for (int j = lane * 4; j < Dq; j += 128) {
        float4 hv = *(const float4*)(hr + j);
#pragma unroll
        for (int p = 0; p < 8; p++) {
            float4 av = *(const float4*)(a_w + (size_t)p * Dq + j);
            acc[p] += hv.x * av.x + hv.y * av.y + hv.z * av.z + hv.w * av.w;
            float4 bv = *(const float4*)(b_w + (size_t)p * Dq + j);
            acc[8 + p] += hv.x * bv.x + hv.y * bv.y + hv.z * bv.z + hv.w * bv.w;
        }
    }
#pragma unroll
    for (int p = 0; p < 16; p++)
#pragma unroll
        for (int m = 16; m; m >>= 1)
            acc[p] += __shfl_xor_sync(0xffffffffu, acc[p], m);

    if (lane < 8) {
        float x = acc[lane] + dt_bias[lane];
        gd[w * Hq + lane] = -expf(A_log[lane]) * softplus_f(x);
    } else if (lane < 16) {
        int p = lane - 8;
        bt[w * Hq + p] = 1.f / (1.f + expf(-acc[lane]));
    }
}

// ---------------- fused conv+SiLU+l2norm for q/k (head dim 128) -------------
__global__ void conv_l2_kernel(const float* __restrict__ P, int colofs,
                               const float* __restrict__ w, float* __restrict__ out)
{
    int gwp = (blockIdx.x * blockDim.x + threadIdx.x) >> 5;
    int lane = threadIdx.x & 31;
    int row = gwp >> 3, hh = gwp & 7;
    int t = row & (Tq - 1);
    int c = hh * 128 + lane * 4;
    const float* base = P + (size_t)row * NFUSE + colofs + c;
    float4 x0 = *(const float4*)base;
    float4 x1 = make_float4(0,0,0,0), x2 = x1, x3 = x1;
    if (t >= 1) x1 = *(const float4*)(base - NFUSE);
    if (t >= 2) x2 = *(const float4*)(base - 2*NFUSE);
    if (t >= 3) x3 = *(const float4*)(base - 3*NFUSE);
    float4 wc0 = *(const float4*)(w + (size_t)(c + 0) * 4);
    float4 wc1 = *(const float4*)(w + (size_t)(c + 1) * 4);
    float4 wc2 = *(const float4*)(w + (size_t)(c + 2) * 4);
    float4 wc3 = *(const float4*)(w + (size_t)(c + 3) * 4);
    float v0 = x0.x*wc0.w + x1.x*wc0.z + x2.x*wc0.y + x3.x*wc0.x;
    float v1 = x0.y*wc1.w + x1.y*wc1.z + x2.y*wc1.y + x3.y*wc1.x;
    float v2 = x0.z*wc2.w + x1.z*wc2.z + x2.z*wc2.y + x3.z*wc2.x;
    float v3 = x0.w*wc3.w + x1.w*wc3.z + x2.w*wc3.y + x3.w*wc3.x;
    v0 = v0 / (1.f + expf(-v0));
    v1 = v1 / (1.f + expf(-v1));
    v2 = v2 / (1.f + expf(-v2));
    v3 = v3 / (1.f + expf(-v3));
    float ss = v0*v0 + v1*v1 + v2*v2 + v3*v3;
#pragma unroll
    for (int m = 16; m; m >>= 1) ss += __shfl_xor_sync(0xffffffffu, ss, m);
    float r = rsqrtf(ss + 1e-6f);
    *(float4*)(out + (size_t)row * KDq + c) =
        make_float4(v0 * r, v1 * r, v2 * r, v3 * r);
}

// ---------------- conv+SiLU for v (elementwise, strided read) ---------------
__global__ void conv_silu_stride(const float* __restrict__ P, int colofs,
                                 const float* __restrict__ w, float* __restrict__ out)
{
    int i = blockIdx.x * blockDim.x + threadIdx.x;
    int c = i % VDq;
    int row = i / VDq;
    int t = row & (Tq - 1);
    const float* base = P + (size_t)row * NFUSE + colofs + c;
    float4 wc = *(const float4*)(w + (size_t)c * 4);
    float acc = base[0] * wc.w;
    if (t >= 1) acc += base[-1 * NFUSE] * wc.z;
    if (t >= 2) acc += base[-2 * NFUSE] * wc.y;
    if (t >= 3) acc += base[-3 * NFUSE] * wc.x;
    out[i] = acc / (1.f + expf(-acc));
}

// ------------------------- gated delta-rule scan (16-col chunks) ------------
// grid (16, H, B) = 256 CTAs, 128 threads. col = tid>>3, rgrp = tid&7 owns
// 16 k-rows (S[16] regs). cp.async double-buffered tile prefetch.
#define TS 16
#define GSTR 160
#define QOFF (TS*GSTR)          // 2560
#define VOFF (2*TS*GSTR)        // 5120
#define GOFF (VOFF + TS*16)     // 5376 (gd 16 + beta 16)
#define SSZ  (GOFF + 32)        // 5408 floats per stage

__global__ void __launch_bounds__(128) scan_kernel(const float* __restrict__ q,
                                                   const float* __restrict__ k,
                                                   const float* __restrict__ v,
                                                   const float* __restrict__ gdec,
                                                   const float* __restrict__ beta,
                                                   float* __restrict__ o)
{
    const int vchunk = blockIdx.x;     // 0..15
    const int h = blockIdx.y;
    const int b = blockIdx.z;
    const int tid = threadIdx.x;
    const int col = tid >> 3;          // 0..15
    const int rgrp = tid & 7;          // 8 groups x 16 rows
    const int c0 = vchunk * 16;

    __shared__ float sbuf[2 * SSZ];
    const uint32_t sb = smem_u32(sbuf);

    float S[16];
#pragma unroll
    for (int i = 0; i < 16; i++) S[i] = 0.f;
    const float scale = 0.08838834764831843f;
    const int NT = Tq / TS;   // 64 tiles

#define SPRE(tt, ss)                                                              \
    {                                                                             \
        const int tb = (tt) * TS;                                                 \
        const uint32_t stb = sb + (uint32_t)(ss) * (SSZ * 4);                     \
        _Pragma("unroll")                                                         \
        for (int j = 0; j < 4; j++) {                                             \
            int idx = tid + j * 128;                                              \
            int s = idx >> 5, f = idx & 31;                                       \
            size_t gofs = ((size_t)(b * Tq + tb + s)) * KDq + h * DKq + f * 4;    \
            uint32_t so = (uint32_t)((s * GSTR + (f >> 2) * 20 + (f & 3) * 4)*4); \
            cp16(stb + so, k + gofs);                                             \
            cp16(stb + QOFF * 4 + so, q + gofs);                                  \
        }                                                                         \
        if (tid < 64) {                                                           \
            int s = tid >> 2, f = tid & 3;                                        \
            size_t gofs = ((size_t)(b * Tq + tb + s)) * VDq + h * DVq + c0 + f*4; \
            cp16(stb + (VOFF + s * 16 + f * 4) * 4, v + gofs);                    \
        } else if (tid < 80) {                                                    \
            int s = tid - 64;                                                     \
            cp4(stb + (GOFF + s) * 4, gdec + (size_t)(b * Tq + tb + s) * Hq + h); \
        } else if (tid < 96) {                                                    \
            int s = tid - 80;                                                     \
            cp4(stb + (GOFF + 16 + s) * 4, beta + (size_t)(b * Tq + tb + s) * Hq + h); \
        }                                                                         \
        cp_commit();                                                              \
    }

    SPRE(0, 0);
    SPRE(1, 1);

    for (int t = 0; t < NT; t++) {
        if (t == NT - 1) cp_wait<0>(); else cp_wait<1>();
        __syncthreads();
        const float* st = sbuf + (t & 1) * SSZ;
        const float* ksb = st;
        const float* qsb = st + QOFF;
        const float* vsb = st + VOFF;
        const float* gsb = st + GOFF;
        const int trow = b * Tq + t * TS;

#pragma unroll
        for (int s = 0; s < TS; s++) {
            const float* kb = ksb + s * GSTR + rgrp * 20;
            const float* qb = qsb + s * GSTR + rgrp * 20;
            float4 k0 = *(const float4*)(kb);
            float4 k1 = *(const float4*)(kb + 4);
            float4 k2 = *(const float4*)(kb + 8);
            float4 k3 = *(const float4*)(kb + 12);
            float kva = k0.x*S[0] + k0.y*S[1] + k0.z*S[2] + k0.w*S[3];
            float kvb = k1.x*S[4] + k1.y*S[5] + k1.z*S[6] + k1.w*S[7];
            float kvc = k2.x*S[8] + k2.y*S[9] + k2.z*S[10] + k2.w*S[11];
            float kvd = k3.x*S[12] + k3.y*S[13] + k3.z*S[14] + k3.w*S[15];
            float kv = (kva + kvb) + (kvc + kvd);
            kv += __shfl_xor_sync(0xffffffffu, kv, 1);
            kv += __shfl_xor_sync(0xffffffffu, kv, 2);
            kv += __shfl_xor_sync(0xffffffffu, kv, 4);
            float eg = expf(gsb[s]);
            float u = (vsb[s * 16 + col] - kv * eg) * gsb[16 + s];
            float4 q0 = *(const float4*)(qb);
            float4 q1 = *(const float4*)(qb + 4);
            float4 q2 = *(const float4*)(qb + 8);
            float4 q3 = *(const float4*)(qb + 12);
            S[0]  = S[0]*eg  + k0.x*u;  S[1]  = S[1]*eg  + k0.y*u;
            S[2]  = S[2]*eg  + k0.z*u;  S[3]  = S[3]*eg  + k0.w*u;
            S[4]  = S[4]*eg  + k1.x*u;  S[5]  = S[5]*eg  + k1.y*u;
            S[6]  = S[6]*eg  + k1.z*u;  S[7]  = S[7]*eg  + k1.w*u;
            S[8]  = S[8]*eg  + k2.x*u;  S[9]  = S[9]*eg  + k2.y*u;
            S[10] = S[10]*eg + k2.z*u;  S[11] = S[11]*eg + k2.w*u;
            S[12] = S[12]*eg + k3.x*u;  S[13] = S[13]*eg + k3.y*u;
            S[14] = S[14]*eg + k3.z*u;  S[15] = S[15]*eg + k3.w*u;
            float oa = q0.x*S[0] + q0.y*S[1] + q0.z*S[2] + q0.w*S[3];
            float ob = q1.x*S[4] + q1.y*S[5] + q1.z*S[6] + q1.w*S[7];
            float oc = q2.x*S[8] + q2.y*S[9] + q2.z*S[10] + q2.w*S[11];
            float od = q3.x*S[12] + q3.y*S[13] + q3.z*S[14] + q3.w*S[15];
            float ot = (oa + ob) + (oc + od);
            ot += __shfl_xor_sync(0xffffffffu, ot, 1);
            ot += __shfl_xor_sync(0xffffffffu, ot, 2);
            ot += __shfl_xor_sync(0xffffffffu, ot, 4);
            if (rgrp == 0)
                o[(size_t)(trow + s) * VDq + h * DVq + c0 + col] = ot * scale;
        }
        __syncthreads();
        if (t + 2 < NT) SPRE(t + 2, t & 1);
    }
#undef SPRE
}

// ------------------------- gated RMSNorm -> bf16 hi/lo ----------------------
__global__ void rmsnorm_gate_kernel(const float* __restrict__ o,
                                    const float* __restrict__ P,   // gate at col 4096
                                    const float* __restrict__ nw,
                                    __nv_bfloat16* __restrict__ oh,
                                    __nv_bfloat16* __restrict__ ol)
{
    int w = (blockIdx.x * blockDim.x + threadIdx.x) >> 5;   // (b,t,h) id
    int lane = threadIdx.x & 31;
    int row = w >> 3, hh = w & 7;
    const float* orow = o + (size_t)w * DVq;
    float4 o0 = *(const float4*)(orow + lane * 4);
    float4 o1 = *(const float4*)(orow + 128 + lane * 4);
    float ss = o0.x * o0.x + o0.y * o0.y + o0.z * o0.z + o0.w * o0.w
             + o1.x * o1.x + o1.y * o1.y + o1.z * o1.z + o1.w * o1.w;
#pragma unroll
    for (int m = 16; m; m >>= 1) ss += __shfl_xor_sync(0xffffffffu, ss, m);
    float r = rsqrtf(ss * (1.f / 256.f) + 1e-5f);
    const float* grow = P + (size_t)row * NFUSE + 4096 + hh * DVq;
    float4 g0 = *(const float4*)(grow + lane * 4);
    float4 g1 = *(const float4*)(grow + 128 + lane * 4);
    float4 w0 = *(const float4*)(nw + lane * 4);
    float4 w1 = *(const float4*)(nw + 128 + lane * 4);
    float f[8];
    f[0] = o0.x * r * w0.x * (g0.x / (1.f + expf(-g0.x)));
    f[1] = o0.y * r * w0.y * (g0.y / (1.f + expf(-g0.y)));
    f[2] = o0.z * r * w0.z * (g0.z / (1.f + expf(-g0.z)));
    f[3] = o0.w * r * w0.w * (g0.w / (1.f + expf(-g0.w)));
    f[4] = o1.x * r * w1.x * (g1.x / (1.f + expf(-g1.x)));
    f[5] = o1.y * r * w1.y * (g1.y / (1.f + expf(-g1.y)));
    f[6] = o1.z * r * w1.z * (g1.z / (1.f + expf(-g1.z)));
    f[7] = o1.w * r * w1.w * (g1.w / (1.f + expf(-g1.w)));
#pragma unroll
    for (int half = 0; half < 2; half++) {
        size_t base = (size_t)w * DVq + half * 128 + lane * 4;
        float a = f[half*4+0], b2 = f[half*4+1], c = f[half*4+2], d = f[half*4+3];
        split4(make_float4(a, b2, c, d), oh + base, ol + base);
    }
}

// ------------------------- launch -------------------------------------------
extern "C" void kernel_launch(void* const* d_in, const int* in_sizes, int n_in,
                              void* d_out, int out_size)
{
    const float* h        = (const float*)d_in[0];
    const float* q_w      = (const float*)d_in[1];
    const float* k_w      = (const float*)d_in[2];
    const float* v_w      = (const float*)d_in[3];
    const float* a_w      = (const float*)d_in[4];
    const float* b_w      = (const float*)d_in[5];
    const float* g_w      = (const float*)d_in[6];
    const float* o_w      = (const float*)d_in[7];
    const float* q_conv_w = (const float*)d_in[8];
    const float* k_conv_w = (const float*)d_in[9];
    const float* v_conv_w = (const float*)d_in[10];
    const float* A_log    = (const float*)d_in[11];
    const float* dt_bias  = (const float*)d_in[12];
    const float* o_norm_w = (const float*)d_in[13];
    float* out = (float*)d_out;

    float *P, *qc, *kc, *vc, *gd, *bt, *orow;
    cudaGetSymbolAddress((void**)&P, g_proj);
    cudaGetSymbolAddress((void**)&qc, g_qc);
    cudaGetSymbolAddress((void**)&kc, g_kc);
    cudaGetSymbolAddress((void**)&vc, g_vc);
    cudaGetSymbolAddress((void**)&gd, g_gd);
    cudaGetSymbolAddress((void**)&bt, g_bt);
    cudaGetSymbolAddress((void**)&orow, g_orow);

    __nv_bfloat16 *hh, *hl, *wh, *wl, *owh, *owl, *onh, *onl;
    cudaGetSymbolAddress((void**)&hh, g_hh);   cudaGetSymbolAddress((void**)&hl, g_hl);
    cudaGetSymbolAddress((void**)&wh, g_wh);   cudaGetSymbolAddress((void**)&wl, g_wl);
    cudaGetSymbolAddress((void**)&owh, g_owh); cudaGetSymbolAddress((void**)&owl, g_owl);
    cudaGetSymbolAddress((void**)&onh, g_onh); cudaGetSymbolAddress((void**)&onl, g_onl);

    cudaFuncSetAttribute(bgemm_nt_split, cudaFuncAttributeMaxDynamicSharedMemorySize, SMEM_GEMM);

    // 0) bf16 hi/lo splits
    cvt_split<<<(Mrows*Dq/4 + 255)/256, 256>>>(h, hh, hl, Mrows*Dq);
    cvt_split_w4<<<(NFUSE*Dq/4 + 255)/256, 256>>>(q_w, k_w, v_w, g_w, wh, wl);
    cvt_split<<<(Dq*VDq/4 + 255)/256, 256>>>(o_w, owh, owl, Dq*VDq);

    // 1) fused q|k|v|gate projection on tensor cores
    bgemm_nt_split<<<dim3(NFUSE/128, Mrows/128), 256, SMEM_GEMM>>>(hh, hl, wh, wl, P, NFUSE);

    // 2) a/b projections -> decay + beta
    proj_ab_kernel<<<(Mrows * 32) / 256, 256>>>(h, a_w, b_w, A_log, dt_bias, gd, bt);

    // 3) conv+SiLU+l2norm for q,k ; conv+SiLU for v
    conv_l2_kernel<<<(Mrows * Hq * 32) / 256, 256>>>(P, 0,    q_conv_w, qc);
    conv_l2_kernel<<<(Mrows * Hq * 32) / 256, 256>>>(P, 1024, k_conv_w, kc);
    conv_silu_stride<<<(Mrows * VDq) / 256, 256>>>(P, 2048, v_conv_w, vc);

    // 4) gated delta-rule recurrence (16-col chunks, 256 CTAs, cp.async pipe)
    scan_kernel<<<dim3(DVq / 16, Hq, Bq), 128>>>(qc, kc, vc, gd, bt, orow);

    // 5) gated RMSNorm (+ bf16 hi/lo split)
    rmsnorm_gate_kernel<<<(Mrows * Hq * 32) / 256, 256>>>(orow, P, o_norm_w, onh, onl);

    // 6) output projection -> d_out
    bgemm_nt_split<<<dim3(Dq/128, Mrows/128), 256, SMEM_GEMM>>>(onh, onl, owh, owl, out, Dq);
}

// round 13
// speedup vs baseline: 1.7559x; 1.2077x over previous
#include <cuda_runtime.h>
#include <cuda_bf16.h>
#include <cuda_fp16.h>
#include <math.h>
#include <stdint.h>

#define Bq 2
#define Tq 1024
#define Dq 2048
#define Hq 8
#define DKq 128
#define DVq 256
#define KDq 1024
#define VDq 2048
#define Mrows (Bq*Tq)   // 2048
#define GK 2048         // K for every big GEMM
#define NFUSE 6144      // q(1024) + k(1024) + v(2048) + gate(2048)

// ------------------------- scratch (device globals) -------------------------
__device__ float g_proj[Mrows*NFUSE];        // fused projection output
__device__ float g_qc[Mrows*KDq];
__device__ float g_kc[Mrows*KDq];
__device__ float g_vc[Mrows*VDq];
__device__ float g_gd[Mrows*Hq];
__device__ float g_bt[Mrows*Hq];
__device__ float g_orow[Mrows*VDq];

// fp16 split (hi/lo) operands; B side hi-only
__device__ __half g_hh[Mrows*Dq],    g_hl[Mrows*Dq];
__device__ __half g_wh[NFUSE*Dq];
__device__ __half g_owh[Dq*VDq];
__device__ __half g_onh[Mrows*VDq],  g_onl[Mrows*VDq];

// ------------------------- helpers ------------------------------------------
__device__ __forceinline__ uint32_t smem_u32(const void* p) {
    uint32_t a;
    asm("{ .reg .u64 t; cvta.to.shared.u64 t, %1; cvt.u32.u64 %0, t; }" : "=r"(a) : "l"(p));
    return a;
}
__device__ __forceinline__ void cp16(uint32_t dst, const void* src) {
    asm volatile("cp.async.cg.shared.global [%0], [%1], 16;" :: "r"(dst), "l"(src));
}
__device__ __forceinline__ void cp4(uint32_t dst, const void* src) {
    asm volatile("cp.async.ca.shared.global [%0], [%1], 4;" :: "r"(dst), "l"(src));
}
__device__ __forceinline__ void cp_commit() {
    asm volatile("cp.async.commit_group;" ::: "memory");
}
template <int N>
__device__ __forceinline__ void cp_wait() {
    asm volatile("cp.async.wait_group %0;" :: "n"(N) : "memory");
}
__device__ __forceinline__ void ldsm_x4(uint32_t addr, uint32_t* r) {
    asm volatile("ldmatrix.sync.aligned.m8n8.x4.shared.b16 {%0,%1,%2,%3}, [%4];"
                 : "=r"(r[0]), "=r"(r[1]), "=r"(r[2]), "=r"(r[3]) : "r"(addr));
}
__device__ __forceinline__ void mma_f16(float* c, const uint32_t* a, const uint32_t* b) {
    asm volatile(
        "mma.sync.aligned.m16n8k16.row.col.f32.f16.f16.f32 "
        "{%0,%1,%2,%3}, {%4,%5,%6,%7}, {%8,%9}, {%0,%1,%2,%3};"
        : "+f"(c[0]), "+f"(c[1]), "+f"(c[2]), "+f"(c[3])
        : "r"(a[0]), "r"(a[1]), "r"(a[2]), "r"(a[3]), "r"(b[0]), "r"(b[1]));
}

// ------------------------- split fp16 HMMA GEMM (2-pass, 2 CTA/SM) ----------
// C = A*B^T, A as fp16 hi/lo pair, B as fp16 hi only.
// A*B ~= Ah*Bh + Al*Bh (dropped A*Bl term ~2^-12 relative, within 1e-3 gate).
#define ROWB 80
#define MATB (128*ROWB)              // 10240 B per matrix
#define STGB (3*MATB)                // Ah,Al,Bh per stage = 30720 B
#define SMEM_GEMM (2*STGB)           // 61440 B

__global__ void __launch_bounds__(256, 2) hgemm_nt_split(
    const __half* __restrict__ Ah, const __half* __restrict__ Al,
    const __half* __restrict__ Bh,
    float* __restrict__ C, int N)
{
    extern __shared__ char smem[];
    const uint32_t sb = smem_u32(smem);
    const int tid = threadIdx.x, wid = tid >> 5, lane = tid & 31;
    const int bm = blockIdx.y * 128, bn = blockIdx.x * 128;
    const int wm = (wid >> 1) * 32;
    const int wn = (wid & 1) * 64;

    float acc[2][8][4];
#pragma unroll
    for (int i = 0; i < 2; i++)
#pragma unroll
        for (int j = 0; j < 8; j++)
#pragma unroll
            for (int l = 0; l < 4; l++) acc[i][j][l] = 0.f;

    const int NC = GK / 32;

#define PREFETCH(cc, ss)                                                          \
    {                                                                             \
        const int kc = (cc) * 32;                                                 \
        const uint32_t stg = sb + (uint32_t)(ss) * STGB;                          \
        _Pragma("unroll")                                                         \
        for (int i = 0; i < 2; i++) {                                             \
            int idx = tid + i * 256;                                              \
            int row = idx >> 2, seg = idx & 3;                                    \
            uint32_t so = (uint32_t)(row * ROWB + seg * 16);                      \
            size_t ea = (size_t)(bm + row) * GK + kc + seg * 8;                   \
            size_t eb = (size_t)(bn + row) * GK + kc + seg * 8;                   \
            cp16(stg + so,            Ah + ea);                                   \
            cp16(stg + MATB + so,     Al + ea);                                   \
            cp16(stg + 2*MATB + so,   Bh + eb);                                   \
        }                                                                         \
        cp_commit();                                                              \
    }

    PREFETCH(0, 0);
    PREFETCH(1, 1);

    const uint32_t a_row = (uint32_t)(wm + (lane & 15));
    const uint32_t a_colb = (uint32_t)((lane >> 4) * 16);
    const uint32_t b_row0 = (uint32_t)(wn + (lane & 7) + ((lane >> 4) << 3));
    const uint32_t b_colb = (uint32_t)(((lane >> 3) & 1) * 16);

    for (int c = 0; c < NC; c++) {
        if (c == NC - 1) cp_wait<0>(); else cp_wait<1>();
        __syncthreads();
        const uint32_t stg = sb + (uint32_t)(c & 1) * STGB;

#pragma unroll
        for (int k16 = 0; k16 < 2; k16++) {
            const uint32_t kb = (uint32_t)(k16 * 32);
            uint32_t a0[2][4], a1[2][4], bb[4][4];

            // pass 1: Ah*Bh (16 distinct accs)
#pragma unroll
            for (int mt = 0; mt < 2; mt++) {
                uint32_t ao = (a_row + mt * 16) * ROWB + kb + a_colb;
                ldsm_x4(stg + ao, a0[mt]);
            }
#pragma unroll
            for (int np = 0; np < 4; np++) {
                uint32_t bo = (b_row0 + np * 16) * ROWB + kb + b_colb;
                ldsm_x4(stg + 2*MATB + bo, bb[np]);
            }
#pragma unroll
            for (int mt = 0; mt < 2; mt++)
#pragma unroll
                for (int np = 0; np < 4; np++) {
                    mma_f16(acc[mt][np*2],   a0[mt], bb[np]);
                    mma_f16(acc[mt][np*2+1], a0[mt], bb[np] + 2);
                }

            // pass 2: Al*Bh (16 distinct accs)
#pragma unroll
            for (int mt = 0; mt < 2; mt++) {
                uint32_t ao = (a_row + mt * 16) * ROWB + kb + a_colb;
                ldsm_x4(stg + MATB + ao, a1[mt]);
            }
#pragma unroll
            for (int mt = 0; mt < 2; mt++)
#pragma unroll
                for (int np = 0; np < 4; np++) {
                    mma_f16(acc[mt][np*2],   a1[mt], bb[np]);
                    mma_f16(acc[mt][np*2+1], a1[mt], bb[np] + 2);
                }
        }
        __syncthreads();
        if (c + 2 < NC) PREFETCH(c + 2, c & 1);
    }
#undef PREFETCH

#pragma unroll
    for (int mt = 0; mt < 2; mt++) {
        int r0 = bm + wm + mt * 16 + (lane >> 2);
#pragma unroll
        for (int nt = 0; nt < 8; nt++) {
            int col = bn + wn + nt * 8 + (lane & 3) * 2;
            float2 v0 = make_float2(acc[mt][nt][0], acc[mt][nt][1]);
            float2 v1 = make_float2(acc[mt][nt][2], acc[mt][nt][3]);
            *(float2*)(C + (size_t)r0 * N + col)       = v0;
            *(float2*)(C + (size_t)(r0 + 8) * N + col) = v1;
        }
    }
}

// ------------------------- fp32 -> fp16 hi/lo split -------------------------
__device__ __forceinline__ void split4h(float4 v, __half* hi, __half* lo) {
    __half hx = __float2half(v.x), hy = __float2half(v.y);
    __half hz = __float2half(v.z), hw = __float2half(v.w);
    __half2 h0, h1, l0, l1;
    h0.x = hx; h0.y = hy; h1.x = hz; h1.y = hw;
    l0.x = __float2half(v.x - __half2float(hx));
    l0.y = __float2half(v.y - __half2float(hy));
    l1.x = __float2half(v.z - __half2float(hz));
    l1.y = __float2half(v.w - __half2float(hw));
    *(__half2*)(hi)     = h0;
    *(__half2*)(hi + 2) = h1;
    *(__half2*)(lo)     = l0;
    *(__half2*)(lo + 2) = l1;
}
__device__ __forceinline__ void cvt4h(float4 v, __half* hi) {
    __half2 h0, h1;
    h0.x = __float2half(v.x); h0.y = __float2half(v.y);
    h1.x = __float2half(v.z); h1.y = __float2half(v.w);
    *(__half2*)(hi)     = h0;
    *(__half2*)(hi + 2) = h1;
}

__global__ void cvt_split(const float* __restrict__ x,
                          __half* __restrict__ hi,
                          __half* __restrict__ lo, int n)
{
    int i = (blockIdx.x * blockDim.x + threadIdx.x) * 4;
    if (i >= n) return;
    split4h(*(const float4*)(x + i), hi + i, lo + i);
}

// fused weight convert (hi only): rows 0-1023 q_w, 1024-2047 k_w, 2048-4095 v_w, 4096-6143 g_w
__global__ void cvt_w4(const float* __restrict__ qw, const float* __restrict__ kw,
                       const float* __restrict__ vw, const float* __restrict__ gw,
                       __half* __restrict__ hi)
{
    int i = (blockIdx.x * blockDim.x + threadIdx.x) * 4;
    int row = i >> 11;
    int col = i & 2047;
    const float* src;
    if (row < 1024)      src = qw + (size_t)row * Dq + col;
    else if (row < 2048) src = kw + (size_t)(row - 1024) * Dq + col;
    else if (row < 4096) src = vw + (size_t)(row - 2048) * Dq + col;
    else                 src = gw + (size_t)(row - 4096) * Dq + col;
    cvt4h(*(const float4*)src, hi + i);
}

__global__ void cvt_h(const float* __restrict__ x, __half* __restrict__ hi, int n)
{
    int i = (blockIdx.x * blockDim.x + threadIdx.x) * 4;
    if (i >= n) return;
    cvt4h(*(const float4*)(x + i), hi + i);
}

// ------------------------- a/b projections -> decay g and beta --------------
__device__ __forceinline__ float softplus_f(float x) {
    return fmaxf(x, 0.f) + log1pf(expf(-fabsf(x)));
}

__global__ void proj_ab_kernel(const float* __restrict__ h,
                               const float* __restrict__ a_w,
                               const float* __restrict__ b_w,
                               const float* __restrict__ A_log,
                               const float* __restrict__ dt_bias,
                               float* __restrict__ gd, float* __restrict__ bt)
{
    int w = (blockIdx.x * blockDim.x + threadIdx.x) >> 5;
    int lane = threadIdx.x & 31;
    if (w >= Mrows) return;
    const float* hr = h + (size_t)w * Dq;
    float acc[16];
#pragma unroll
    for (int p = 0; p < 16; p++) acc[p] = 0.f;
    for (int j = lane * 4; j < Dq; j += 128) {
        float4 hv = *(const float4*)(hr + j);
#pragma unroll
        for (int p = 0; p < 8; p++) {
            float4 av = *(const float4*)(a_w + (size_t)p * Dq + j);
            acc[p] += hv.x * av.x + hv.y * av.y + hv.z * av.z + hv.w * av.w;
            float4 bv = *(const float4*)(b_w + (size_t)p * Dq + j);
            acc[8 + p] += hv.x * bv.x + hv.y * bv.y + hv.z * bv.z + hv.w * bv.w;
        }
    }
#pragma unroll
    for (int p = 0; p < 16; p++)
#pragma unroll
        for (int m = 16; m; m >>= 1)
            acc[p] += __shfl_xor_sync(0xffffffffu, acc[p], m);

    if (lane < 8) {
        float x = acc[lane] + dt_bias[lane];
        gd[w * Hq + lane] = -expf(A_log[lane]) * softplus_f(x);
    } else if (lane < 16) {
        int p = lane - 8;
        bt[w * Hq + p] = 1.f / (1.f + expf(-acc[lane]));
    }
}

// ---------------- fused conv+SiLU+l2norm for q/k (head dim 128) -------------
__global__ void conv_l2_kernel(const float* __restrict__ P, int colofs,
                               const float* __restrict__ w, float* __restrict__ out)
{
    int gwp = (blockIdx.x * blockDim.x + threadIdx.x) >> 5;
    int lane = threadIdx.x & 31;
    int row = gwp >> 3, hh = gwp & 7;
    int t = row & (Tq - 1);
    int c = hh * 128 + lane * 4;
    const float* base = P + (size_t)row * NFUSE + colofs + c;
    float4 x0 = *(const float4*)base;
    float4 x1 = make_float4(0,0,0,0), x2 = x1, x3 = x1;
    if (t >= 1) x1 = *(const float4*)(base - NFUSE);
    if (t >= 2) x2 = *(const float4*)(base - 2*NFUSE);
    if (t >= 3) x3 = *(const float4*)(base - 3*NFUSE);
    float4 wc0 = *(const float4*)(w + (size_t)(c + 0) * 4);
    float4 wc1 = *(const float4*)(w + (size_t)(c + 1) * 4);
    float4 wc2 = *(const float4*)(w + (size_t)(c + 2) * 4);
    float4 wc3 = *(const float4*)(w + (size_t)(c + 3) * 4);
    float v0 = x0.x*wc0.w + x1.x*wc0.z + x2.x*wc0.y + x3.x*wc0.x;
    float v1 = x0.y*wc1.w + x1.y*wc1.z + x2.y*wc1.y + x3.y*wc1.x;
    float v2 = x0.z*wc2.w + x1.z*wc2.z + x2.z*wc2.y + x3.z*wc2.x;
    float v3 = x0.w*wc3.w + x1.w*wc3.z + x2.w*wc3.y + x3.w*wc3.x;
    v0 = v0 / (1.f + expf(-v0));
    v1 = v1 / (1.f + expf(-v1));
    v2 = v2 / (1.f + expf(-v2));
    v3 = v3 / (1.f + expf(-v3));
    float ss = v0*v0 + v1*v1 + v2*v2 + v3*v3;
#pragma unroll
    for (int m = 16; m; m >>= 1) ss += __shfl_xor_sync(0xffffffffu, ss, m);
    float r = rsqrtf(ss + 1e-6f);
    *(float4*)(out + (size_t)row * KDq + c) =
        make_float4(v0 * r, v1 * r, v2 * r, v3 * r);
}

// ---------------- conv+SiLU for v (elementwise, strided read) ---------------
__global__ void conv_silu_stride(const float* __restrict__ P, int colofs,
                                 const float* __restrict__ w, float* __restrict__ out)
{
    int i = blockIdx.x * blockDim.x + threadIdx.x;
    int c = i % VDq;
    int row = i / VDq;
    int t = row & (Tq - 1);
    const float* base = P + (size_t)row * NFUSE + colofs + c;
    float4 wc = *(const float4*)(w + (size_t)c * 4);
    float acc = base[0] * wc.w;
    if (t >= 1) acc += base[-1 * NFUSE] * wc.z;
    if (t >= 2) acc += base[-2 * NFUSE] * wc.y;
    if (t >= 3) acc += base[-3 * NFUSE] * wc.x;
    out[i] = acc / (1.f + expf(-acc));
}

// ------------------------- gated delta-rule scan (16-col chunks) ------------
#define TS 16
#define GSTR 160
#define QOFF (TS*GSTR)
#define VOFF (2*TS*GSTR)
#define GOFF (VOFF + TS*16)
#define SSZ  (GOFF + 32)

__global__ void __launch_bounds__(128) scan_kernel(const float* __restrict__ q,
                                                   const float* __restrict__ k,
                                                   const float* __restrict__ v,
                                                   const float* __restrict__ gdec,
                                                   const float* __restrict__ beta,
                                                   float* __restrict__ o)
{
    const int vchunk = blockIdx.x;
    const int h = blockIdx.y;
    const int b = blockIdx.z;
    const int tid = threadIdx.x;
    const int col = tid >> 3;
    const int rgrp = tid & 7;
    const int c0 = vchunk * 16;

    __shared__ float sbuf[2 * SSZ];
    const uint32_t sb = smem_u32(sbuf);

    float S[16];
#pragma unroll
    for (int i = 0; i < 16; i++) S[i] = 0.f;
    const float scale = 0.08838834764831843f;
    const int NT = Tq / TS;

#define SPRE(tt, ss)                                                              \
    {                                                                             \
        const int tb = (tt) * TS;                                                 \
        const uint32_t stb = sb + (uint32_t)(ss) * (SSZ * 4);                     \
        _Pragma("unroll")                                                         \
        for (int j = 0; j < 4; j++) {                                             \
            int idx = tid + j * 128;                                              \
            int s = idx >> 5, f = idx & 31;                                       \
            size_t gofs = ((size_t)(b * Tq + tb + s)) * KDq + h * DKq + f * 4;    \
            uint32_t so = (uint32_t)((s * GSTR + (f >> 2) * 20 + (f & 3) * 4)*4); \
            cp16(stb + so, k + gofs);                                             \
            cp16(stb + QOFF * 4 + so, q + gofs);                                  \
        }                                                                         \
        if (tid < 64) {                                                           \
            int s = tid >> 2, f = tid & 3;                                        \
            size_t gofs = ((size_t)(b * Tq + tb + s)) * VDq + h * DVq + c0 + f*4; \
            cp16(stb + (VOFF + s * 16 + f * 4) * 4, v + gofs);                    \
        } else if (tid < 80) {                                                    \
            int s = tid - 64;                                                     \
            cp4(stb + (GOFF + s) * 4, gdec + (size_t)(b * Tq + tb + s) * Hq + h); \
        } else if (tid < 96) {                                                    \
            int s = tid - 80;                                                     \
            cp4(stb + (GOFF + 16 + s) * 4, beta + (size_t)(b * Tq + tb + s) * Hq + h); \
        }                                                                         \
        cp_commit();                                                              \
    }

    SPRE(0, 0);
    SPRE(1, 1);

    for (int t = 0; t < NT; t++) {
        if (t == NT - 1) cp_wait<0>(); else cp_wait<1>();
        __syncthreads();
        const float* st = sbuf + (t & 1) * SSZ;
        const float* ksb = st;
        const float* qsb = st + QOFF;
        const float* vsb = st + VOFF;
        const float* gsb = st + GOFF;
        const int trow = b * Tq + t * TS;

#pragma unroll
        for (int s = 0; s < TS; s++) {
            const float* kb = ksb + s * GSTR + rgrp * 20;
            const float* qb = qsb + s * GSTR + rgrp * 20;
            float4 k0 = *(const float4*)(kb);
            float4 k1 = *(const float4*)(kb + 4);
            float4 k2 = *(const float4*)(kb + 8);
            float4 k3 = *(const float4*)(kb + 12);
            float kva = k0.x*S[0] + k0.y*S[1] + k0.z*S[2] + k0.w*S[3];
            float kvb = k1.x*S[4] + k1.y*S[5] + k1.z*S[6] + k1.w*S[7];
            float kvc = k2.x*S[8] + k2.y*S[9] + k2.z*S[10] + k2.w*S[11];
            float kvd = k3.x*S[12] + k3.y*S[13] + k3.z*S[14] + k3.w*S[15];
            float kv = (kva + kvb) + (kvc + kvd);
            kv += __shfl_xor_sync(0xffffffffu, kv, 1);
            kv += __shfl_xor_sync(0xffffffffu, kv, 2);
            kv += __shfl_xor_sync(0xffffffffu, kv, 4);
            float eg = expf(gsb[s]);
            float u = (vsb[s * 16 + col] - kv * eg) * gsb[16 + s];
            float4 q0 = *(const float4*)(qb);
            float4 q1 = *(const float4*)(qb + 4);
            float4 q2 = *(const float4*)(qb + 8);
            float4 q3 = *(const float4*)(qb + 12);
            S[0]  = S[0]*eg  + k0.x*u;  S[1]  = S[1]*eg  + k0.y*u;
            S[2]  = S[2]*eg  + k0.z*u;  S[3]  = S[3]*eg  + k0.w*u;
            S[4]  = S[4]*eg  + k1.x*u;  S[5]  = S[5]*eg  + k1.y*u;
            S[6]  = S[6]*eg  + k1.z*u;  S[7]  = S[7]*eg  + k1.w*u;
            S[8]  = S[8]*eg  + k2.x*u;  S[9]  = S[9]*eg  + k2.y*u;
            S[10] = S[10]*eg + k2.z*u;  S[11] = S[11]*eg + k2.w*u;
            S[12] = S[12]*eg + k3.x*u;  S[13] = S[13]*eg + k3.y*u;
            S[14] = S[14]*eg + k3.z*u;  S[15] = S[15]*eg + k3.w*u;
            float oa = q0.x*S[0] + q0.y*S[1] + q0.z*S[2] + q0.w*S[3];
            float ob = q1.x*S[4] + q1.y*S[5] + q1.z*S[6] + q1.w*S[7];
            float oc = q2.x*S[8] + q2.y*S[9] + q2.z*S[10] + q2.w*S[11];
            float od = q3.x*S[12] + q3.y*S[13] + q3.z*S[14] + q3.w*S[15];
            float ot = (oa + ob) + (oc + od);
            ot += __shfl_xor_sync(0xffffffffu, ot, 1);
            ot += __shfl_xor_sync(0xffffffffu, ot, 2);
            ot += __shfl_xor_sync(0xffffffffu, ot, 4);
            if (rgrp == 0)
                o[(size_t)(trow + s) * VDq + h * DVq + c0 + col] = ot * scale;
        }
        __syncthreads();
        if (t + 2 < NT) SPRE(t + 2, t & 1);
    }
#undef SPRE
}

// ------------------------- gated RMSNorm -> fp16 hi/lo ----------------------
__global__ void rmsnorm_gate_kernel(const float* __restrict__ o,
                                    const float* __restrict__ P,   // gate at col 4096
                                    const float* __restrict__ nw,
                                    __half* __restrict__ oh,
                                    __half* __restrict__ ol)
{
    int w = (blockIdx.x * blockDim.x + threadIdx.x) >> 5;
    int lane = threadIdx.x & 31;
    int row = w >> 3, hh = w & 7;
    const float* orow = o + (size_t)w * DVq;
    float4 o0 = *(const float4*)(orow + lane * 4);
    float4 o1 = *(const float4*)(orow + 128 + lane * 4);
    float ss = o0.x * o0.x + o0.y * o0.y + o0.z * o0.z + o0.w * o0.w
             + o1.x * o1.x + o1.y * o1.y + o1.z * o1.z + o1.w * o1.w;
#pragma unroll
    for (int m = 16; m; m >>= 1) ss += __shfl_xor_sync(0xffffffffu, ss, m);
    float r = rsqrtf(ss * (1.f / 256.f) + 1e-5f);
    const float* grow = P + (size_t)row * NFUSE + 4096 + hh * DVq;
    float4 g0 = *(const float4*)(grow + lane * 4);
    float4 g1 = *(const float4*)(grow + 128 + lane * 4);
    float4 w0 = *(const float4*)(nw + lane * 4);
    float4 w1 = *(const float4*)(nw + 128 + lane * 4);
    float f[8];
    f[0] = o0.x * r * w0.x * (g0.x / (1.f + expf(-g0.x)));
    f[1] = o0.y * r * w0.y * (g0.y / (1.f + expf(-g0.y)));
    f[2] = o0.z * r * w0.z * (g0.z / (1.f + expf(-g0.z)));
    f[3] = o0.w * r * w0.w * (g0.w / (1.f + expf(-g0.w)));
    f[4] = o1.x * r * w1.x * (g1.x / (1.f + expf(-g1.x)));
    f[5] = o1.y * r * w1.y * (g1.y / (1.f + expf(-g1.y)));
    f[6] = o1.z * r * w1.z * (g1.z / (1.f + expf(-g1.z)));
    f[7] = o1.w * r * w1.w * (g1.w / (1.f + expf(-g1.w)));
#pragma unroll
    for (int half = 0; half < 2; half++) {
        size_t base = (size_t)w * DVq + half * 128 + lane * 4;
        float a = f[half*4+0], b2 = f[half*4+1], c = f[half*4+2], d = f[half*4+3];
        split4h(make_float4(a, b2, c, d), oh + base, ol + base);
    }
}

// ------------------------- launch -------------------------------------------
extern "C" void kernel_launch(void* const* d_in, const int* in_sizes, int n_in,
                              void* d_out, int out_size)
{
    const float* h        = (const float*)d_in[0];
    const float* q_w      = (const float*)d_in[1];
    const float* k_w      = (const float*)d_in[2];
    const float* v_w      = (const float*)d_in[3];
    const float* a_w      = (const float*)d_in[4];
    const float* b_w      = (const float*)d_in[5];
    const float* g_w      = (const float*)d_in[6];
    const float* o_w      = (const float*)d_in[7];
    const float* q_conv_w = (const float*)d_in[8];
    const float* k_conv_w = (const float*)d_in[9];
    const float* v_conv_w = (const float*)d_in[10];
    const float* A_log    = (const float*)d_in[11];
    const float* dt_bias  = (const float*)d_in[12];
    const float* o_norm_w = (const float*)d_in[13];
    float* out = (float*)d_out;

    float *P, *qc, *kc, *vc, *gd, *bt, *orow;
    cudaGetSymbolAddress((void**)&P, g_proj);
    cudaGetSymbolAddress((void**)&qc, g_qc);
    cudaGetSymbolAddress((void**)&kc, g_kc);
    cudaGetSymbolAddress((void**)&vc, g_vc);
    cudaGetSymbolAddress((void**)&gd, g_gd);
    cudaGetSymbolAddress((void**)&bt, g_bt);
    cudaGetSymbolAddress((void**)&orow, g_orow);

    __half *hh, *hl, *wh, *owh, *onh, *onl;
    cudaGetSymbolAddress((void**)&hh, g_hh);   cudaGetSymbolAddress((void**)&hl, g_hl);
    cudaGetSymbolAddress((void**)&wh, g_wh);
    cudaGetSymbolAddress((void**)&owh, g_owh);
    cudaGetSymbolAddress((void**)&onh, g_onh); cudaGetSymbolAddress((void**)&onl, g_onl);

    cudaFuncSetAttribute(hgemm_nt_split, cudaFuncAttributeMaxDynamicSharedMemorySize, SMEM_GEMM);

    // 0) fp16 hi/lo splits (A sides) and hi-only (B sides)
    cvt_split<<<(Mrows*Dq/4 + 255)/256, 256>>>(h, hh, hl, Mrows*Dq);
    cvt_w4<<<(NFUSE*Dq/4 + 255)/256, 256>>>(q_w, k_w, v_w, g_w, wh);
    cvt_h<<<(Dq*VDq/4 + 255)/256, 256>>>(o_w, owh, Dq*VDq);

    // 1) fused q|k|v|gate projection on tensor cores (fp16 2-pass split)
    hgemm_nt_split<<<dim3(NFUSE/128, Mrows/128), 256, SMEM_GEMM>>>(hh, hl, wh, P, NFUSE);

    // 2) a/b projections -> decay + beta
    proj_ab_kernel<<<(Mrows * 32) / 256, 256>>>(h, a_w, b_w, A_log, dt_bias, gd, bt);

    // 3) conv+SiLU+l2norm for q,k ; conv+SiLU for v
    conv_l2_kernel<<<(Mrows * Hq * 32) / 256, 256>>>(P, 0,    q_conv_w, qc);
    conv_l2_kernel<<<(Mrows * Hq * 32) / 256, 256>>>(P, 1024, k_conv_w, kc);
    conv_silu_stride<<<(Mrows * VDq) / 256, 256>>>(P, 2048, v_conv_w, vc);

    // 4) gated delta-rule recurrence (16-col chunks, 256 CTAs, cp.async pipe)
    scan_kernel<<<dim3(DVq / 16, Hq, Bq), 128>>>(qc, kc, vc, gd, bt, orow);

    // 5) gated RMSNorm (+ fp16 hi/lo split)
    rmsnorm_gate_kernel<<<(Mrows * Hq * 32) / 256, 256>>>(orow, P, o_norm_w, onh, onl);

    // 6) output projection -> d_out
    hgemm_nt_split<<<dim3(Dq/128, Mrows/128), 256, SMEM_GEMM>>>(onh, onl, owh, out, Dq);
}